// round 1
// baseline (speedup 1.0000x reference)
#include <cuda_runtime.h>
#include <math.h>

#define DIMM   256
#define TT     8192
#define BB     4
#define HEADSN 8
#define DH     32
#define NB     128          // TT / BUCKET
#define BUCKET 64
#define FFD    1024
#define DEPTHN 6
#define MROWS  (BB*TT)      // 32768
#define BHN    (BB*HEADSN)  // 32

// ---------------- static device scratch (no allocs allowed) ----------------
__device__ float g_y [MROWS*DIMM];
__device__ float g_h [MROWS*DIMM];
__device__ float g_q [MROWS*DIMM];
__device__ float g_kv[MROWS*2*DIMM];
__device__ float g_o [MROWS*DIMM];
__device__ float g_ff[MROWS*FFD];
__device__ float g_sq[BHN*NB*DH];
__device__ float g_sk[BHN*NB*DH];
__device__ float g_top[BHN*NB];
__device__ int   g_idx[BHN*NB];

// ---------------- x (b,dim,t) -> y (b,t,dim) + positional add ----------------
__global__ void pos_add_kernel(const float* __restrict__ x, const float* __restrict__ pe0,
                               const float* __restrict__ pe1, float* __restrict__ y) {
    __shared__ float tile[32][33];
    int b  = blockIdx.z;
    int d0 = blockIdx.y * 32;
    int t0 = blockIdx.x * 32;
    int tx = threadIdx.x, ty = threadIdx.y;   // (32, 8)
    const float* xb = x + (size_t)b * DIMM * TT;
    #pragma unroll
    for (int i = 0; i < 32; i += 8)
        tile[ty + i][tx] = xb[(size_t)(d0 + ty + i) * TT + t0 + tx];
    __syncthreads();
    float* yb = y + (size_t)b * TT * DIMM;
    #pragma unroll
    for (int i = 0; i < 32; i += 8) {
        int t = t0 + ty + i;
        int d = d0 + tx;
        yb[(size_t)t * DIMM + d] =
            tile[tx][ty + i] + pe0[(size_t)(t >> 6) * DIMM + d] + pe1[(size_t)(t & 63) * DIMM + d];
    }
}

// ---------------- h (b,t,dim) -> out (b,dim,t) ----------------
__global__ void out_transpose_kernel(const float* __restrict__ hin, float* __restrict__ out) {
    __shared__ float tile[32][33];
    int b  = blockIdx.z;
    int d0 = blockIdx.y * 32;
    int t0 = blockIdx.x * 32;
    int tx = threadIdx.x, ty = threadIdx.y;
    const float* hb = hin + (size_t)b * TT * DIMM;
    #pragma unroll
    for (int i = 0; i < 32; i += 8)
        tile[ty + i][tx] = hb[(size_t)(t0 + ty + i) * DIMM + d0 + tx];
    __syncthreads();
    float* ob = out + (size_t)b * DIMM * TT;
    #pragma unroll
    for (int i = 0; i < 32; i += 8)
        ob[(size_t)(d0 + ty + i) * TT + t0 + tx] = tile[tx][ty + i];
}

// ---------------- layernorm over last dim (256) ----------------
__global__ void ln_kernel(const float* __restrict__ in, float* __restrict__ out,
                          const float* __restrict__ g, const float* __restrict__ b) {
    int row  = blockIdx.x * 8 + (threadIdx.x >> 5);
    int lane = threadIdx.x & 31;
    const float* r = in + (size_t)row * DIMM;
    float v[8];
    float s = 0.f;
    #pragma unroll
    for (int i = 0; i < 8; i++) { v[i] = r[lane + i * 32]; s += v[i]; }
    #pragma unroll
    for (int off = 16; off; off >>= 1) s += __shfl_xor_sync(0xffffffffu, s, off);
    float m = s * (1.0f / DIMM);
    float var = 0.f;
    #pragma unroll
    for (int i = 0; i < 8; i++) { float d = v[i] - m; var += d * d; }
    #pragma unroll
    for (int off = 16; off; off >>= 1) var += __shfl_xor_sync(0xffffffffu, var, off);
    var *= (1.0f / DIMM);
    float inv = rsqrtf(var + 1e-5f);
    float* o = out + (size_t)row * DIMM;
    #pragma unroll
    for (int i = 0; i < 8; i++) {
        int c = lane + i * 32;
        o[c] = (v[i] - m) * inv * g[c] + b[c];
    }
}

// ---------------- generic fp32 GEMM: C = A@W (+bias)(+gelu)(+resid) ----------------
// A: (M, K) lda, W: (K, N) ldw, C: (M, N) ldc, resid uses ldc. M,N % 64 == 0, K % 16 == 0.
__global__ void gemm_kernel(const float* __restrict__ A, int lda,
                            const float* __restrict__ W, int ldw,
                            const float* __restrict__ bias,
                            const float* __restrict__ resid,
                            float* __restrict__ C, int ldc,
                            int K, int gelu) {
    __shared__ float As[16][68];
    __shared__ float Bs[16][68];
    int m0 = blockIdx.y * 64, n0 = blockIdx.x * 64;
    int tid = threadIdx.x;
    int tx = tid & 15, ty = tid >> 4;
    float acc[4][4] = {};
    for (int k0 = 0; k0 < K; k0 += 16) {
        #pragma unroll
        for (int i = tid; i < 64 * 16; i += 256) {
            int m = i >> 4, kk = i & 15;
            As[kk][m] = A[(size_t)(m0 + m) * lda + k0 + kk];
        }
        #pragma unroll
        for (int i = tid; i < 16 * 64; i += 256) {
            int kk = i >> 6, n = i & 63;
            Bs[kk][n] = W[(size_t)(k0 + kk) * ldw + n0 + n];
        }
        __syncthreads();
        #pragma unroll
        for (int kk = 0; kk < 16; kk++) {
            float a[4], bb[4];
            #pragma unroll
            for (int i = 0; i < 4; i++) a[i] = As[kk][ty * 4 + i];
            #pragma unroll
            for (int j = 0; j < 4; j++) bb[j] = Bs[kk][tx * 4 + j];
            #pragma unroll
            for (int i = 0; i < 4; i++)
                #pragma unroll
                for (int j = 0; j < 4; j++)
                    acc[i][j] = fmaf(a[i], bb[j], acc[i][j]);
        }
        __syncthreads();
    }
    #pragma unroll
    for (int i = 0; i < 4; i++) {
        int m = m0 + ty * 4 + i;
        #pragma unroll
        for (int j = 0; j < 4; j++) {
            int n = n0 + tx * 4 + j;
            float c = acc[i][j];
            if (bias) c += bias[n];
            if (gelu) c = 0.5f * c * (1.0f + erff(c * 0.70710678118654752f));
            if (resid) c += resid[(size_t)m * ldc + n];
            C[(size_t)m * ldc + n] = c;
        }
    }
}

// ---------------- bucket mean summaries of q, k ----------------
__global__ void summary_kernel(const float* __restrict__ q, const float* __restrict__ kv) {
    // grid (NB, BHN), block DH
    int u = blockIdx.x, bh = blockIdx.y;
    int b = bh >> 3, h = bh & 7;
    int e = threadIdx.x;
    const float* qp = q  + ((size_t)(b * TT + u * BUCKET)) * DIMM     + h * DH + e;
    const float* kp = kv + ((size_t)(b * TT + u * BUCKET)) * (2*DIMM) + h * DH + e;
    float sq = 0.f, sk = 0.f;
    #pragma unroll 8
    for (int i = 0; i < BUCKET; i++) {
        sq += qp[(size_t)i * DIMM];
        sk += kp[(size_t)i * (2*DIMM)];
    }
    g_sq[((size_t)bh * NB + u) * DH + e] = sq * (1.0f / BUCKET);
    g_sk[((size_t)bh * NB + u) * DH + e] = sk * (1.0f / BUCKET);
}

// ---------------- routing: top prob + argmax per (bh, bucket) ----------------
__global__ void routing_kernel() {
    // grid (BHN), block NB
    int bh = blockIdx.x;
    int i  = threadIdx.x;
    __shared__ float ssk[NB][DH];
    const float* base = g_sk + (size_t)bh * NB * DH;
    for (int idx = i; idx < NB * DH; idx += NB) ssk[idx / DH][idx % DH] = base[idx];
    float sq[DH];
    const float* sqp = g_sq + ((size_t)bh * NB + i) * DH;
    #pragma unroll
    for (int e = 0; e < DH; e++) sq[e] = sqp[e];
    __syncthreads();
    const float sc = 0.17677669529663687f * (1.0f / 0.75f);  // dh^-0.5 / TEMP
    float mx = -1e30f; int am = 0;
    for (int j = 0; j < NB; j++) {
        float d = 0.f;
        #pragma unroll
        for (int e = 0; e < DH; e++) d = fmaf(sq[e], ssk[j][e], d);
        d *= sc;
        if (d > mx) { mx = d; am = j; }
    }
    float sum = 0.f;
    for (int j = 0; j < NB; j++) {
        float d = 0.f;
        #pragma unroll
        for (int e = 0; e < DH; e++) d = fmaf(sq[e], ssk[j][e], d);
        sum += expf(d * sc - mx);
    }
    g_top[bh * NB + i] = 1.0f / sum;   // max prob = exp(0)/sum after shift
    g_idx[bh * NB + i] = am;
}

// ---------------- bucketed attention: one block per (bucket, bh) ----------------
__global__ void attn_kernel(const float* __restrict__ q, const float* __restrict__ kv,
                            float* __restrict__ o) {
    int u = blockIdx.x, bh = blockIdx.y;
    int b = bh >> 3, h = bh & 7;
    __shared__ float sQ[64][DH];
    __shared__ float sK[128][DH + 1];
    __shared__ float sV[128][DH];
    __shared__ float sP[8][128];
    int tid = threadIdx.x;
    int warp = tid >> 5, lane = tid & 31;
    float top = g_top[bh * NB + u];
    int  ridx = g_idx[bh * NB + u];
    const float* qbase = q  + ((size_t)(b * TT + u * BUCKET)) * DIMM + h * DH;
    const float* kself = kv + ((size_t)(b * TT + u    * BUCKET)) * (2*DIMM) + h * DH;
    const float* krout = kv + ((size_t)(b * TT + ridx * BUCKET)) * (2*DIMM) + h * DH;
    for (int i = tid; i < 64 * DH; i += 256) {
        int r = i >> 5, e = i & 31;
        sQ[r][e]      = qbase[(size_t)r * DIMM + e];
        sK[r][e]      = top * krout[(size_t)r * (2*DIMM) + e];
        sV[r][e]      = top * krout[(size_t)r * (2*DIMM) + DIMM + e];
        sK[64 + r][e] =       kself[(size_t)r * (2*DIMM) + e];
        sV[64 + r][e] =       kself[(size_t)r * (2*DIMM) + DIMM + e];
    }
    __syncthreads();
    const float scale = 0.17677669529663687f;  // dh^-0.5
    float* ob = o + ((size_t)(b * TT + u * BUCKET)) * DIMM + h * DH;
    for (int rr = 0; rr < 8; rr++) {
        int r = warp * 8 + rr;
        float d[4];
        #pragma unroll
        for (int c = 0; c < 4; c++) {
            int j = lane + c * 32;
            float acc = 0.f;
            #pragma unroll
            for (int e = 0; e < DH; e++) acc = fmaf(sQ[r][e], sK[j][e], acc);
            d[c] = acc * scale;
        }
        float mx = fmaxf(fmaxf(d[0], d[1]), fmaxf(d[2], d[3]));
        #pragma unroll
        for (int off = 16; off; off >>= 1) mx = fmaxf(mx, __shfl_xor_sync(0xffffffffu, mx, off));
        float p[4], s = 0.f;
        #pragma unroll
        for (int c = 0; c < 4; c++) { p[c] = __expf(d[c] - mx); s += p[c]; }
        #pragma unroll
        for (int off = 16; off; off >>= 1) s += __shfl_xor_sync(0xffffffffu, s, off);
        float inv = 1.0f / s;
        #pragma unroll
        for (int c = 0; c < 4; c++) sP[warp][lane + c * 32] = p[c] * inv;
        __syncwarp();
        float acc = 0.f;
        #pragma unroll
        for (int j = 0; j < 128; j++) acc = fmaf(sP[warp][j], sV[j][lane], acc);
        ob[(size_t)r * DIMM + lane] = acc;
        __syncwarp();
    }
}

// ---------------- host orchestration ----------------
extern "C" void kernel_launch(void* const* d_in, const int* in_sizes, int n_in,
                              void* d_out, int out_size) {
    const float* x     = (const float*)d_in[0];
    const float* pe0   = (const float*)d_in[1];
    const float* pe1   = (const float*)d_in[2];
    const float* ln1_g = (const float*)d_in[3];
    const float* ln1_b = (const float*)d_in[4];
    const float* Wq    = (const float*)d_in[5];
    const float* Wkv   = (const float*)d_in[6];
    const float* Wo    = (const float*)d_in[7];
    const float* bo    = (const float*)d_in[8];
    const float* ln2_g = (const float*)d_in[9];
    const float* ln2_b = (const float*)d_in[10];
    const float* W1    = (const float*)d_in[11];
    const float* b1    = (const float*)d_in[12];
    const float* W2    = (const float*)d_in[13];
    const float* b2    = (const float*)d_in[14];
    const float* gf    = (const float*)d_in[15];
    const float* bf    = (const float*)d_in[16];
    float* out = (float*)d_out;

    float *y, *h, *q, *kv, *o, *ff;
    cudaGetSymbolAddress((void**)&y,  g_y);
    cudaGetSymbolAddress((void**)&h,  g_h);
    cudaGetSymbolAddress((void**)&q,  g_q);
    cudaGetSymbolAddress((void**)&kv, g_kv);
    cudaGetSymbolAddress((void**)&o,  g_o);
    cudaGetSymbolAddress((void**)&ff, g_ff);

    dim3 tb(32, 8);
    dim3 tg(TT / 32, DIMM / 32, BB);

    pos_add_kernel<<<tg, tb>>>(x, pe0, pe1, y);

    for (int L = 0; L < DEPTHN; L++) {
        const float* wq  = Wq  + (size_t)L * DIMM * DIMM;
        const float* wkv = Wkv + (size_t)L * DIMM * 2 * DIMM;
        const float* wo  = Wo  + (size_t)L * DIMM * DIMM;
        const float* bo_ = bo  + (size_t)L * DIMM;
        const float* w1  = W1  + (size_t)L * DIMM * FFD;
        const float* bb1 = b1  + (size_t)L * FFD;
        const float* w2  = W2  + (size_t)L * FFD * DIMM;
        const float* bb2 = b2  + (size_t)L * DIMM;

        ln_kernel<<<MROWS / 8, 256>>>(y, h, ln1_g + (size_t)L * DIMM, ln1_b + (size_t)L * DIMM);
        gemm_kernel<<<dim3(DIMM / 64, MROWS / 64), 256>>>(h, DIMM, wq,  DIMM,     nullptr, nullptr, q,  DIMM,     DIMM, 0);
        gemm_kernel<<<dim3(2*DIMM/64, MROWS / 64), 256>>>(h, DIMM, wkv, 2*DIMM,   nullptr, nullptr, kv, 2*DIMM,   DIMM, 0);
        summary_kernel<<<dim3(NB, BHN), DH>>>(q, kv);
        routing_kernel<<<BHN, NB>>>();
        attn_kernel<<<dim3(NB, BHN), 256>>>(q, kv, o);
        gemm_kernel<<<dim3(DIMM / 64, MROWS / 64), 256>>>(o, DIMM, wo, DIMM, bo_, y, y, DIMM, DIMM, 0);
        ln_kernel<<<MROWS / 8, 256>>>(y, h, ln2_g + (size_t)L * DIMM, ln2_b + (size_t)L * DIMM);
        gemm_kernel<<<dim3(FFD / 64,  MROWS / 64), 256>>>(h,  DIMM, w1, FFD,  bb1, nullptr, ff, FFD,  DIMM, 1);
        gemm_kernel<<<dim3(DIMM / 64, MROWS / 64), 256>>>(ff, FFD,  w2, DIMM, bb2, y,       y,  DIMM, FFD,  0);
    }

    ln_kernel<<<MROWS / 8, 256>>>(y, h, gf, bf);
    out_transpose_kernel<<<tg, tb>>>(h, out);
    (void)in_sizes; (void)n_in; (void)out_size;
}

// round 3
// speedup vs baseline: 2.2573x; 2.2573x over previous
#include <cuda_runtime.h>
#include <cuda_bf16.h>
#include <math.h>
#include <cstdint>

#define DIMM   256
#define TT     8192
#define BB     4
#define HEADSN 8
#define DH     32
#define NB     128
#define BUCKET 64
#define FFD    1024
#define DEPTHN 6
#define MROWS  (BB*TT)
#define BHN    (BB*HEADSN)

// ======================= static device scratch =======================
__device__ float g_y [MROWS*DIMM];
__device__ float g_q [MROWS*DIMM];
__device__ float g_kv[MROWS*2*DIMM];
__device__ __nv_bfloat16 g_hh [MROWS*DIMM],  g_hl [MROWS*DIMM];
__device__ __nv_bfloat16 g_ohi[MROWS*DIMM],  g_olo[MROWS*DIMM];
__device__ __nv_bfloat16 g_ffh[MROWS*FFD],   g_ffl[MROWS*FFD];
__device__ __nv_bfloat16 g_wqh [DEPTHN*DIMM*DIMM],   g_wql [DEPTHN*DIMM*DIMM];
__device__ __nv_bfloat16 g_wkvh[DEPTHN*DIMM*2*DIMM], g_wkvl[DEPTHN*DIMM*2*DIMM];
__device__ __nv_bfloat16 g_woh [DEPTHN*DIMM*DIMM],   g_wol [DEPTHN*DIMM*DIMM];
__device__ __nv_bfloat16 g_w1h [DEPTHN*DIMM*FFD],    g_w1l [DEPTHN*DIMM*FFD];
__device__ __nv_bfloat16 g_w2h [DEPTHN*FFD*DIMM],    g_w2l [DEPTHN*FFD*DIMM];
__device__ float g_sq[BHN*NB*DH];
__device__ float g_sk[BHN*NB*DH];
__device__ float g_top[BHN*NB];
__device__ int   g_idx[BHN*NB];

// ======================= helpers =======================
__device__ __forceinline__ uint32_t smem_u32(const void* p) {
    uint32_t a;
    asm("{ .reg .u64 t; cvta.to.shared.u64 t, %1; cvt.u32.u64 %0, t; }" : "=r"(a) : "l"(p));
    return a;
}

#define MMA_BF16(c, a, b) \
    asm volatile("mma.sync.aligned.m16n8k16.row.col.f32.bf16.bf16.f32 " \
        "{%0,%1,%2,%3}, {%4,%5,%6,%7}, {%8,%9}, {%0,%1,%2,%3};" \
        : "+f"((c)[0]), "+f"((c)[1]), "+f"((c)[2]), "+f"((c)[3]) \
        : "r"((a)[0]), "r"((a)[1]), "r"((a)[2]), "r"((a)[3]), "r"((b)[0]), "r"((b)[1]))

#define LDSM_X4(r, addr) \
    asm volatile("ldmatrix.sync.aligned.m8n8.x4.shared.b16 {%0,%1,%2,%3}, [%4];" \
        : "=r"((r)[0]), "=r"((r)[1]), "=r"((r)[2]), "=r"((r)[3]) : "r"(addr))

#define CP_ASYNC16(dst, src) \
    asm volatile("cp.async.cg.shared.global [%0], [%1], 16;" :: "r"(dst), "l"(src))
#define CP_ASYNC_WAIT() \
    asm volatile("cp.async.commit_group;\n\tcp.async.wait_group 0;" ::: "memory")

// ======================= small kernels =======================
__global__ void pos_add_kernel(const float* __restrict__ x, const float* __restrict__ pe0,
                               const float* __restrict__ pe1, float* __restrict__ y) {
    __shared__ float tile[32][33];
    int b = blockIdx.z, d0 = blockIdx.y * 32, t0 = blockIdx.x * 32;
    int tx = threadIdx.x, ty = threadIdx.y;
    const float* xb = x + (size_t)b * DIMM * TT;
    #pragma unroll
    for (int i = 0; i < 32; i += 8)
        tile[ty + i][tx] = xb[(size_t)(d0 + ty + i) * TT + t0 + tx];
    __syncthreads();
    float* yb = y + (size_t)b * TT * DIMM;
    #pragma unroll
    for (int i = 0; i < 32; i += 8) {
        int t = t0 + ty + i, d = d0 + tx;
        yb[(size_t)t * DIMM + d] =
            tile[tx][ty + i] + pe0[(size_t)(t >> 6) * DIMM + d] + pe1[(size_t)(t & 63) * DIMM + d];
    }
}

__global__ void out_transpose_kernel(const float* __restrict__ hin, float* __restrict__ out) {
    __shared__ float tile[32][33];
    int b = blockIdx.z, d0 = blockIdx.y * 32, t0 = blockIdx.x * 32;
    int tx = threadIdx.x, ty = threadIdx.y;
    const float* hb = hin + (size_t)b * TT * DIMM;
    #pragma unroll
    for (int i = 0; i < 32; i += 8)
        tile[ty + i][tx] = hb[(size_t)(t0 + ty + i) * DIMM + d0 + tx];
    __syncthreads();
    float* ob = out + (size_t)b * DIMM * TT;
    #pragma unroll
    for (int i = 0; i < 32; i += 8)
        ob[(size_t)(d0 + ty + i) * TT + t0 + tx] = tile[tx][ty + i];
}

__global__ void ln_kernel(const float* __restrict__ in, float* __restrict__ out,
                          const float* __restrict__ g, const float* __restrict__ b) {
    int row = blockIdx.x * 8 + (threadIdx.x >> 5);
    int lane = threadIdx.x & 31;
    const float* r = in + (size_t)row * DIMM;
    float v[8], s = 0.f;
    #pragma unroll
    for (int i = 0; i < 8; i++) { v[i] = r[lane + i * 32]; s += v[i]; }
    #pragma unroll
    for (int off = 16; off; off >>= 1) s += __shfl_xor_sync(0xffffffffu, s, off);
    float m = s * (1.0f / DIMM), var = 0.f;
    #pragma unroll
    for (int i = 0; i < 8; i++) { float d = v[i] - m; var += d * d; }
    #pragma unroll
    for (int off = 16; off; off >>= 1) var += __shfl_xor_sync(0xffffffffu, var, off);
    float inv = rsqrtf(var * (1.0f / DIMM) + 1e-5f);
    float* o = out + (size_t)row * DIMM;
    #pragma unroll
    for (int i = 0; i < 8; i++) {
        int c = lane + i * 32;
        o[c] = (v[i] - m) * inv * g[c] + b[c];
    }
}

__global__ void ln_pair_kernel(const float* __restrict__ in,
                               __nv_bfloat16* __restrict__ oh, __nv_bfloat16* __restrict__ ol,
                               const float* __restrict__ g, const float* __restrict__ b) {
    int row = blockIdx.x * 8 + (threadIdx.x >> 5);
    int lane = threadIdx.x & 31;
    const float* r = in + (size_t)row * DIMM;
    float v[8], s = 0.f;
    #pragma unroll
    for (int i = 0; i < 8; i++) { v[i] = r[lane + i * 32]; s += v[i]; }
    #pragma unroll
    for (int off = 16; off; off >>= 1) s += __shfl_xor_sync(0xffffffffu, s, off);
    float m = s * (1.0f / DIMM), var = 0.f;
    #pragma unroll
    for (int i = 0; i < 8; i++) { float d = v[i] - m; var += d * d; }
    #pragma unroll
    for (int off = 16; off; off >>= 1) var += __shfl_xor_sync(0xffffffffu, var, off);
    float inv = rsqrtf(var * (1.0f / DIMM) + 1e-5f);
    #pragma unroll
    for (int i = 0; i < 8; i++) {
        int c = lane + i * 32;
        float val = (v[i] - m) * inv * g[c] + b[c];
        __nv_bfloat16 h = __float2bfloat16(val);
        size_t o = (size_t)row * DIMM + c;
        oh[o] = h;
        ol[o] = __float2bfloat16(val - __bfloat162float(h));
    }
}

__global__ void wconv_kernel(const float* __restrict__ W, __nv_bfloat16* __restrict__ Th,
                             __nv_bfloat16* __restrict__ Tl, int K, int N) {
    __shared__ float t[32][33];
    int l = blockIdx.z;
    const float* Wl = W + (size_t)l * K * N;
    size_t ob = (size_t)l * K * N;
    int n0 = blockIdx.x * 32, k0 = blockIdx.y * 32;
    int tx = threadIdx.x, ty = threadIdx.y;
    #pragma unroll
    for (int i = 0; i < 32; i += 8)
        t[ty + i][tx] = Wl[(size_t)(k0 + ty + i) * N + n0 + tx];
    __syncthreads();
    #pragma unroll
    for (int i = 0; i < 32; i += 8) {
        float v = t[tx][ty + i];
        size_t o = ob + (size_t)(n0 + ty + i) * K + k0 + tx;
        __nv_bfloat16 h = __float2bfloat16(v);
        Th[o] = h;
        Tl[o] = __float2bfloat16(v - __bfloat162float(h));
    }
}

// ======================= HMMA bf16 hi/lo GEMM =======================
// C(M,N) = A(M,K) @ B^T where B given as WT (N,K) row-major. 3-term bf16 split.
// CTA: 128x128, K-chunk 64. 8 warps: 2(m) x 4(n), warp tile 64x32.
#define AHI_OFF 0
#define ALO_OFF 16384
#define BHI_OFF 32768
#define BLO_OFF 49152
#define GEMM_SMEM 65536

__global__ __launch_bounds__(256)
void hmma_gemm(const __nv_bfloat16* __restrict__ Ahi, const __nv_bfloat16* __restrict__ Alo, int lda,
               const __nv_bfloat16* __restrict__ Bhi, const __nv_bfloat16* __restrict__ Blo, int ldb,
               const float* __restrict__ bias, const float* __restrict__ resid,
               float* __restrict__ Cf, __nv_bfloat16* __restrict__ Chi, __nv_bfloat16* __restrict__ Clo,
               int ldc, int K, int gelu) {
    extern __shared__ char smem[];
    uint32_t sb = smem_u32(smem);
    int tid = threadIdx.x;
    int lane = tid & 31, wid = tid >> 5;
    int wm = wid >> 2, wn = wid & 3;          // warp grid 2x4
    int m0 = blockIdx.y * 128, n0 = blockIdx.x * 128;

    float acc[4][4][4];
    #pragma unroll
    for (int i = 0; i < 4; i++)
        #pragma unroll
        for (int j = 0; j < 4; j++)
            #pragma unroll
            for (int k = 0; k < 4; k++) acc[i][j][k] = 0.f;

    // precomputed ldmatrix lane addressing
    int a_row = (lane & 15);                  // within 16-row tile
    int a_kh  = (lane >> 4);                  // k half (0/1)
    int b_sub = (lane >> 3);                  // 0..3
    int b_row = ((b_sub >> 1) << 3) + (lane & 7);  // within 16-row (2 n-tiles)
    int b_kh  = (b_sub & 1);

    for (int k0 = 0; k0 < K; k0 += 64) {
        // ---- load 4 tiles (128 rows x 64 bf16 each), XOR-swizzled ----
        #pragma unroll
        for (int p = 0; p < 4; ++p) {
            int lin = p * 256 + tid;          // 0..1023
            int r = lin >> 3, kb = lin & 7;
            uint32_t soff = (uint32_t)(r * 128 + ((kb ^ (r & 7)) << 4));
            CP_ASYNC16(sb + AHI_OFF + soff, Ahi + (size_t)(m0 + r) * lda + k0 + kb * 8);
            CP_ASYNC16(sb + ALO_OFF + soff, Alo + (size_t)(m0 + r) * lda + k0 + kb * 8);
            CP_ASYNC16(sb + BHI_OFF + soff, Bhi + (size_t)(n0 + r) * ldb + k0 + kb * 8);
            CP_ASYNC16(sb + BLO_OFF + soff, Blo + (size_t)(n0 + r) * ldb + k0 + kb * 8);
        }
        CP_ASYNC_WAIT();
        __syncthreads();

        // ---- compute: 4 k-steps of 16 ----
        #pragma unroll
        for (int ks = 0; ks < 4; ++ks) {
            // B fragments: 2 ldmatrix.x4 cover 4 n-tiles, hi & lo
            uint32_t bh[4][2], bl[4][2];
            #pragma unroll
            for (int pair = 0; pair < 2; ++pair) {
                int row = wn * 32 + pair * 16 + b_row;
                int kb = ks * 2 + b_kh;
                uint32_t addr = sb + (uint32_t)(row * 128 + ((kb ^ (row & 7)) << 4));
                uint32_t rg[4];
                LDSM_X4(rg, addr + BHI_OFF);
                bh[pair * 2][0] = rg[0]; bh[pair * 2][1] = rg[1];
                bh[pair * 2 + 1][0] = rg[2]; bh[pair * 2 + 1][1] = rg[3];
                LDSM_X4(rg, addr + BLO_OFF);
                bl[pair * 2][0] = rg[0]; bl[pair * 2][1] = rg[1];
                bl[pair * 2 + 1][0] = rg[2]; bl[pair * 2 + 1][1] = rg[3];
            }
            #pragma unroll
            for (int mt = 0; mt < 4; ++mt) {
                int row = wm * 64 + mt * 16 + a_row;
                int kb = ks * 2 + a_kh;
                uint32_t addr = sb + (uint32_t)(row * 128 + ((kb ^ (row & 7)) << 4));
                uint32_t ah[4], al[4];
                LDSM_X4(ah, addr + AHI_OFF);
                LDSM_X4(al, addr + ALO_OFF);
                #pragma unroll
                for (int nt = 0; nt < 4; ++nt) {
                    MMA_BF16(acc[mt][nt], ah, bh[nt]);
                    MMA_BF16(acc[mt][nt], ah, bl[nt]);
                    MMA_BF16(acc[mt][nt], al, bh[nt]);
                }
            }
        }
        __syncthreads();
    }

    // ---- epilogue: fragment -> global ----
    int rbase = m0 + wm * 64 + (lane >> 2);
    int cbase = n0 + wn * 32 + (lane & 3) * 2;
    #pragma unroll
    for (int mt = 0; mt < 4; ++mt) {
        #pragma unroll
        for (int nt = 0; nt < 4; ++nt) {
            #pragma unroll
            for (int half = 0; half < 2; ++half) {
                int gm = rbase + mt * 16 + half * 8;
                int gn = cbase + nt * 8;
                float v0 = acc[mt][nt][half * 2 + 0];
                float v1 = acc[mt][nt][half * 2 + 1];
                if (bias) { v0 += bias[gn]; v1 += bias[gn + 1]; }
                if (gelu) {
                    v0 = 0.5f * v0 * (1.0f + erff(v0 * 0.70710678118654752f));
                    v1 = 0.5f * v1 * (1.0f + erff(v1 * 0.70710678118654752f));
                }
                size_t go = (size_t)gm * ldc + gn;
                if (resid) { v0 += resid[go]; v1 += resid[go + 1]; }
                if (Cf) {
                    *reinterpret_cast<float2*>(Cf + go) = make_float2(v0, v1);
                } else {
                    __nv_bfloat16 h0 = __float2bfloat16(v0);
                    __nv_bfloat16 h1 = __float2bfloat16(v1);
                    __nv_bfloat162 hh2; hh2.x = h0; hh2.y = h1;
                    __nv_bfloat162 ll2;
                    ll2.x = __float2bfloat16(v0 - __bfloat162float(h0));
                    ll2.y = __float2bfloat16(v1 - __bfloat162float(h1));
                    *reinterpret_cast<__nv_bfloat162*>(Chi + go) = hh2;
                    *reinterpret_cast<__nv_bfloat162*>(Clo + go) = ll2;
                }
            }
        }
    }
}

// ======================= attention =======================
__global__ void summary_kernel(const float* __restrict__ q, const float* __restrict__ kv) {
    int u = blockIdx.x, bh = blockIdx.y;
    int b = bh >> 3, h = bh & 7;
    int e = threadIdx.x;
    const float* qp = q  + ((size_t)(b * TT + u * BUCKET)) * DIMM       + h * DH + e;
    const float* kp = kv + ((size_t)(b * TT + u * BUCKET)) * (2 * DIMM) + h * DH + e;
    float sq = 0.f, sk = 0.f;
    #pragma unroll 8
    for (int i = 0; i < BUCKET; i++) {
        sq += qp[(size_t)i * DIMM];
        sk += kp[(size_t)i * (2 * DIMM)];
    }
    g_sq[((size_t)bh * NB + u) * DH + e] = sq * (1.0f / BUCKET);
    g_sk[((size_t)bh * NB + u) * DH + e] = sk * (1.0f / BUCKET);
}

__global__ void routing_kernel() {
    int bh = blockIdx.x;
    int i = threadIdx.x;
    __shared__ float ssk[NB][DH];
    const float* base = g_sk + (size_t)bh * NB * DH;
    for (int idx = i; idx < NB * DH; idx += NB) ssk[idx / DH][idx % DH] = base[idx];
    float sq[DH];
    const float* sqp = g_sq + ((size_t)bh * NB + i) * DH;
    #pragma unroll
    for (int e = 0; e < DH; e++) sq[e] = sqp[e];
    __syncthreads();
    const float sc = 0.17677669529663687f * (1.0f / 0.75f);
    float mx = -1e30f; int am = 0;
    for (int j = 0; j < NB; j++) {
        float d = 0.f;
        #pragma unroll
        for (int e = 0; e < DH; e++) d = fmaf(sq[e], ssk[j][e], d);
        d *= sc;
        if (d > mx) { mx = d; am = j; }
    }
    float sum = 0.f;
    for (int j = 0; j < NB; j++) {
        float d = 0.f;
        #pragma unroll
        for (int e = 0; e < DH; e++) d = fmaf(sq[e], ssk[j][e], d);
        sum += expf(d * sc - mx);
    }
    g_top[bh * NB + i] = 1.0f / sum;
    g_idx[bh * NB + i] = am;
}

__global__ void attn_kernel(const float* __restrict__ q, const float* __restrict__ kv,
                            __nv_bfloat16* __restrict__ ohi, __nv_bfloat16* __restrict__ olo) {
    int u = blockIdx.x, bh = blockIdx.y;
    int b = bh >> 3, h = bh & 7;
    __shared__ float sQ[64][DH];
    __shared__ float sK[128][DH + 1];
    __shared__ float sV[128][DH];
    __shared__ float sP[8][128];
    int tid = threadIdx.x;
    int warp = tid >> 5, lane = tid & 31;
    float top = g_top[bh * NB + u];
    int ridx = g_idx[bh * NB + u];
    const float* qbase = q  + ((size_t)(b * TT + u * BUCKET)) * DIMM + h * DH;
    const float* kself = kv + ((size_t)(b * TT + u    * BUCKET)) * (2 * DIMM) + h * DH;
    const float* krout = kv + ((size_t)(b * TT + ridx * BUCKET)) * (2 * DIMM) + h * DH;
    for (int i = tid; i < 64 * DH; i += 256) {
        int r = i >> 5, e = i & 31;
        sQ[r][e]      = qbase[(size_t)r * DIMM + e];
        sK[r][e]      = top * krout[(size_t)r * (2 * DIMM) + e];
        sV[r][e]      = top * krout[(size_t)r * (2 * DIMM) + DIMM + e];
        sK[64 + r][e] =       kself[(size_t)r * (2 * DIMM) + e];
        sV[64 + r][e] =       kself[(size_t)r * (2 * DIMM) + DIMM + e];
    }
    __syncthreads();
    const float scale = 0.17677669529663687f;
    size_t obase = ((size_t)(b * TT + u * BUCKET)) * DIMM + h * DH;
    for (int rr = 0; rr < 8; rr++) {
        int r = warp * 8 + rr;
        float d[4];
        #pragma unroll
        for (int c = 0; c < 4; c++) {
            int j = lane + c * 32;
            float a = 0.f;
            #pragma unroll
            for (int e = 0; e < DH; e++) a = fmaf(sQ[r][e], sK[j][e], a);
            d[c] = a * scale;
        }
        float mx = fmaxf(fmaxf(d[0], d[1]), fmaxf(d[2], d[3]));
        #pragma unroll
        for (int off = 16; off; off >>= 1) mx = fmaxf(mx, __shfl_xor_sync(0xffffffffu, mx, off));
        float p[4], s = 0.f;
        #pragma unroll
        for (int c = 0; c < 4; c++) { p[c] = __expf(d[c] - mx); s += p[c]; }
        #pragma unroll
        for (int off = 16; off; off >>= 1) s += __shfl_xor_sync(0xffffffffu, s, off);
        float inv = 1.0f / s;
        #pragma unroll
        for (int c = 0; c < 4; c++) sP[warp][lane + c * 32] = p[c] * inv;
        __syncwarp();
        float a = 0.f;
        #pragma unroll
        for (int j = 0; j < 128; j++) a = fmaf(sP[warp][j], sV[j][lane], a);
        __nv_bfloat16 hb = __float2bfloat16(a);
        ohi[obase + (size_t)r * DIMM + lane] = hb;
        olo[obase + (size_t)r * DIMM + lane] = __float2bfloat16(a - __bfloat162float(hb));
        __syncwarp();
    }
}

// ======================= host orchestration =======================
extern "C" void kernel_launch(void* const* d_in, const int* in_sizes, int n_in,
                              void* d_out, int out_size) {
    const float* x     = (const float*)d_in[0];
    const float* pe0   = (const float*)d_in[1];
    const float* pe1   = (const float*)d_in[2];
    const float* ln1_g = (const float*)d_in[3];
    const float* ln1_b = (const float*)d_in[4];
    const float* Wq    = (const float*)d_in[5];
    const float* Wkv   = (const float*)d_in[6];
    const float* Wo    = (const float*)d_in[7];
    const float* bo    = (const float*)d_in[8];
    const float* ln2_g = (const float*)d_in[9];
    const float* ln2_b = (const float*)d_in[10];
    const float* W1    = (const float*)d_in[11];
    const float* b1    = (const float*)d_in[12];
    const float* W2    = (const float*)d_in[13];
    const float* b2    = (const float*)d_in[14];
    const float* gf    = (const float*)d_in[15];
    const float* bf    = (const float*)d_in[16];
    float* out = (float*)d_out;

    cudaFuncSetAttribute(hmma_gemm, cudaFuncAttributeMaxDynamicSharedMemorySize, GEMM_SMEM);

    float *y, *q, *kv;
    __nv_bfloat16 *hh, *hl, *ohi, *olo, *ffh, *ffl;
    __nv_bfloat16 *wqh, *wql, *wkvh, *wkvl, *woh, *wol, *w1h, *w1l, *w2h, *w2l;
    cudaGetSymbolAddress((void**)&y, g_y);
    cudaGetSymbolAddress((void**)&q, g_q);
    cudaGetSymbolAddress((void**)&kv, g_kv);
    cudaGetSymbolAddress((void**)&hh, g_hh);   cudaGetSymbolAddress((void**)&hl, g_hl);
    cudaGetSymbolAddress((void**)&ohi, g_ohi); cudaGetSymbolAddress((void**)&olo, g_olo);
    cudaGetSymbolAddress((void**)&ffh, g_ffh); cudaGetSymbolAddress((void**)&ffl, g_ffl);
    cudaGetSymbolAddress((void**)&wqh, g_wqh);   cudaGetSymbolAddress((void**)&wql, g_wql);
    cudaGetSymbolAddress((void**)&wkvh, g_wkvh); cudaGetSymbolAddress((void**)&wkvl, g_wkvl);
    cudaGetSymbolAddress((void**)&woh, g_woh);   cudaGetSymbolAddress((void**)&wol, g_wol);
    cudaGetSymbolAddress((void**)&w1h, g_w1h);   cudaGetSymbolAddress((void**)&w1l, g_w1l);
    cudaGetSymbolAddress((void**)&w2h, g_w2h);   cudaGetSymbolAddress((void**)&w2l, g_w2l);

    dim3 tb(32, 8);
    wconv_kernel<<<dim3(DIMM / 32,   DIMM / 32, DEPTHN), tb>>>(Wq,  wqh,  wql,  DIMM, DIMM);
    wconv_kernel<<<dim3(2*DIMM / 32, DIMM / 32, DEPTHN), tb>>>(Wkv, wkvh, wkvl, DIMM, 2*DIMM);
    wconv_kernel<<<dim3(DIMM / 32,   DIMM / 32, DEPTHN), tb>>>(Wo,  woh,  wol,  DIMM, DIMM);
    wconv_kernel<<<dim3(FFD / 32,    DIMM / 32, DEPTHN), tb>>>(W1,  w1h,  w1l,  DIMM, FFD);
    wconv_kernel<<<dim3(DIMM / 32,   FFD / 32,  DEPTHN), tb>>>(W2,  w2h,  w2l,  FFD,  DIMM);

    dim3 tg(TT / 32, DIMM / 32, BB);
    pos_add_kernel<<<tg, tb>>>(x, pe0, pe1, y);

    for (int L = 0; L < DEPTHN; L++) {
        const float* bo_ = bo + (size_t)L * DIMM;
        const float* bb1 = b1 + (size_t)L * FFD;
        const float* bb2 = b2 + (size_t)L * DIMM;
        size_t oq   = (size_t)L * DIMM * DIMM;
        size_t okv  = (size_t)L * DIMM * 2 * DIMM;
        size_t off1 = (size_t)L * DIMM * FFD;

        ln_pair_kernel<<<MROWS / 8, 256>>>(y, hh, hl, ln1_g + (size_t)L * DIMM, ln1_b + (size_t)L * DIMM);
        hmma_gemm<<<dim3(2, MROWS / 128), 256, GEMM_SMEM>>>(hh, hl, DIMM, wqh + oq, wql + oq, DIMM,
            nullptr, nullptr, q, nullptr, nullptr, DIMM, DIMM, 0);
        hmma_gemm<<<dim3(4, MROWS / 128), 256, GEMM_SMEM>>>(hh, hl, DIMM, wkvh + okv, wkvl + okv, DIMM,
            nullptr, nullptr, kv, nullptr, nullptr, 2 * DIMM, DIMM, 0);
        summary_kernel<<<dim3(NB, BHN), DH>>>(q, kv);
        routing_kernel<<<BHN, NB>>>();
        attn_kernel<<<dim3(NB, BHN), 256>>>(q, kv, ohi, olo);
        hmma_gemm<<<dim3(2, MROWS / 128), 256, GEMM_SMEM>>>(ohi, olo, DIMM, woh + oq, wol + oq, DIMM,
            bo_, y, y, nullptr, nullptr, DIMM, DIMM, 0);
        ln_pair_kernel<<<MROWS / 8, 256>>>(y, hh, hl, ln2_g + (size_t)L * DIMM, ln2_b + (size_t)L * DIMM);
        hmma_gemm<<<dim3(8, MROWS / 128), 256, GEMM_SMEM>>>(hh, hl, DIMM, w1h + off1, w1l + off1, DIMM,
            bb1, nullptr, nullptr, ffh, ffl, FFD, DIMM, 1);
        hmma_gemm<<<dim3(2, MROWS / 128), 256, GEMM_SMEM>>>(ffh, ffl, FFD, w2h + off1, w2l + off1, FFD,
            bb2, y, y, nullptr, nullptr, DIMM, FFD, 0);
    }

    ln_kernel<<<MROWS / 8, 256>>>(y, q, gf, bf);
    out_transpose_kernel<<<tg, tb>>>(q, out);
    (void)in_sizes; (void)n_in; (void)out_size;
}

// round 4
// speedup vs baseline: 2.5140x; 1.1137x over previous
#include <cuda_runtime.h>
#include <cuda_bf16.h>
#include <math.h>
#include <cstdint>

#define DIMM   256
#define TT     8192
#define BB     4
#define HEADSN 8
#define DH     32
#define NB     128
#define BUCKET 64
#define FFD    1024
#define DEPTHN 6
#define MROWS  (BB*TT)
#define BHN    (BB*HEADSN)
#define QKVD   768

// ======================= static device scratch =======================
__device__ float g_y  [MROWS*DIMM];
__device__ float g_qkv[MROWS*QKVD];
__device__ __nv_bfloat16 g_hh [MROWS*DIMM],  g_hl [MROWS*DIMM];
__device__ __nv_bfloat16 g_ohi[MROWS*DIMM],  g_olo[MROWS*DIMM];
__device__ __nv_bfloat16 g_ffh[MROWS*FFD],   g_ffl[MROWS*FFD];
__device__ __nv_bfloat16 g_wqkvh[DEPTHN*QKVD*DIMM], g_wqkvl[DEPTHN*QKVD*DIMM];
__device__ __nv_bfloat16 g_woh [DEPTHN*DIMM*DIMM],  g_wol [DEPTHN*DIMM*DIMM];
__device__ __nv_bfloat16 g_w1h [DEPTHN*DIMM*FFD],   g_w1l [DEPTHN*DIMM*FFD];
__device__ __nv_bfloat16 g_w2h [DEPTHN*FFD*DIMM],   g_w2l [DEPTHN*FFD*DIMM];
__device__ float g_sq[BHN*NB*DH];
__device__ float g_sk[BHN*NB*DH];
__device__ float g_top[BHN*NB];
__device__ int   g_idx[BHN*NB];

// ======================= helpers =======================
__device__ __forceinline__ uint32_t smem_u32(const void* p) {
    uint32_t a;
    asm("{ .reg .u64 t; cvta.to.shared.u64 t, %1; cvt.u32.u64 %0, t; }" : "=r"(a) : "l"(p));
    return a;
}

#define MMA_BF16(c, a, b) \
    asm volatile("mma.sync.aligned.m16n8k16.row.col.f32.bf16.bf16.f32 " \
        "{%0,%1,%2,%3}, {%4,%5,%6,%7}, {%8,%9}, {%0,%1,%2,%3};" \
        : "+f"((c)[0]), "+f"((c)[1]), "+f"((c)[2]), "+f"((c)[3]) \
        : "r"((a)[0]), "r"((a)[1]), "r"((a)[2]), "r"((a)[3]), "r"((b)[0]), "r"((b)[1]))

#define LDSM_X4(r, addr) \
    asm volatile("ldmatrix.sync.aligned.m8n8.x4.shared.b16 {%0,%1,%2,%3}, [%4];" \
        : "=r"((r)[0]), "=r"((r)[1]), "=r"((r)[2]), "=r"((r)[3]) : "r"(addr))

#define CP_ASYNC16(dst, src) \
    asm volatile("cp.async.cg.shared.global [%0], [%1], 16;" :: "r"(dst), "l"(src))
#define CP_COMMIT()  asm volatile("cp.async.commit_group;" ::: "memory")
#define CP_WAIT(n)   asm volatile("cp.async.wait_group %0;" :: "n"(n) : "memory")

// ======================= small kernels =======================
__global__ void pos_add_kernel(const float* __restrict__ x, const float* __restrict__ pe0,
                               const float* __restrict__ pe1, float* __restrict__ y) {
    __shared__ float tile[32][33];
    int b = blockIdx.z, d0 = blockIdx.y * 32, t0 = blockIdx.x * 32;
    int tx = threadIdx.x, ty = threadIdx.y;
    const float* xb = x + (size_t)b * DIMM * TT;
    #pragma unroll
    for (int i = 0; i < 32; i += 8)
        tile[ty + i][tx] = xb[(size_t)(d0 + ty + i) * TT + t0 + tx];
    __syncthreads();
    float* yb = y + (size_t)b * TT * DIMM;
    #pragma unroll
    for (int i = 0; i < 32; i += 8) {
        int t = t0 + ty + i, d = d0 + tx;
        yb[(size_t)t * DIMM + d] =
            tile[tx][ty + i] + pe0[(size_t)(t >> 6) * DIMM + d] + pe1[(size_t)(t & 63) * DIMM + d];
    }
}

__global__ void out_transpose_kernel(const float* __restrict__ hin, float* __restrict__ out) {
    __shared__ float tile[32][33];
    int b = blockIdx.z, d0 = blockIdx.y * 32, t0 = blockIdx.x * 32;
    int tx = threadIdx.x, ty = threadIdx.y;
    const float* hb = hin + (size_t)b * TT * DIMM;
    #pragma unroll
    for (int i = 0; i < 32; i += 8)
        tile[ty + i][tx] = hb[(size_t)(t0 + ty + i) * DIMM + d0 + tx];
    __syncthreads();
    float* ob = out + (size_t)b * DIMM * TT;
    #pragma unroll
    for (int i = 0; i < 32; i += 8)
        ob[(size_t)(d0 + ty + i) * TT + t0 + tx] = tile[tx][ty + i];
}

__global__ void ln_kernel(const float* __restrict__ in, float* __restrict__ out,
                          const float* __restrict__ g, const float* __restrict__ b) {
    int row = blockIdx.x * 8 + (threadIdx.x >> 5);
    int lane = threadIdx.x & 31;
    const float* r = in + (size_t)row * DIMM;
    float v[8], s = 0.f;
    #pragma unroll
    for (int i = 0; i < 8; i++) { v[i] = r[lane + i * 32]; s += v[i]; }
    #pragma unroll
    for (int off = 16; off; off >>= 1) s += __shfl_xor_sync(0xffffffffu, s, off);
    float m = s * (1.0f / DIMM), var = 0.f;
    #pragma unroll
    for (int i = 0; i < 8; i++) { float d = v[i] - m; var += d * d; }
    #pragma unroll
    for (int off = 16; off; off >>= 1) var += __shfl_xor_sync(0xffffffffu, var, off);
    float inv = rsqrtf(var * (1.0f / DIMM) + 1e-5f);
    float* o = out + (size_t)row * DIMM;
    #pragma unroll
    for (int i = 0; i < 8; i++) {
        int c = lane + i * 32;
        o[c] = (v[i] - m) * inv * g[c] + b[c];
    }
}

__global__ void ln_pair_kernel(const float* __restrict__ in,
                               __nv_bfloat16* __restrict__ oh, __nv_bfloat16* __restrict__ ol,
                               const float* __restrict__ g, const float* __restrict__ b) {
    int row = blockIdx.x * 8 + (threadIdx.x >> 5);
    int lane = threadIdx.x & 31;
    const float* r = in + (size_t)row * DIMM;
    float v[8], s = 0.f;
    #pragma unroll
    for (int i = 0; i < 8; i++) { v[i] = r[lane + i * 32]; s += v[i]; }
    #pragma unroll
    for (int off = 16; off; off >>= 1) s += __shfl_xor_sync(0xffffffffu, s, off);
    float m = s * (1.0f / DIMM), var = 0.f;
    #pragma unroll
    for (int i = 0; i < 8; i++) { float d = v[i] - m; var += d * d; }
    #pragma unroll
    for (int off = 16; off; off >>= 1) var += __shfl_xor_sync(0xffffffffu, var, off);
    float inv = rsqrtf(var * (1.0f / DIMM) + 1e-5f);
    #pragma unroll
    for (int i = 0; i < 8; i++) {
        int c = lane + i * 32;
        float val = (v[i] - m) * inv * g[c] + b[c];
        __nv_bfloat16 h = __float2bfloat16(val);
        size_t o = (size_t)row * DIMM + c;
        oh[o] = h;
        ol[o] = __float2bfloat16(val - __bfloat162float(h));
    }
}

// W (K,N) fp32 -> WT (N,K) bf16 hi/lo; layer stride decoupled for packed buffers
__global__ void wconv_kernel(const float* __restrict__ W, __nv_bfloat16* __restrict__ Th,
                             __nv_bfloat16* __restrict__ Tl, int K, int N, size_t lstride) {
    __shared__ float t[32][33];
    int l = blockIdx.z;
    const float* Wl = W + (size_t)l * K * N;
    size_t ob = (size_t)l * lstride;
    int n0 = blockIdx.x * 32, k0 = blockIdx.y * 32;
    int tx = threadIdx.x, ty = threadIdx.y;
    #pragma unroll
    for (int i = 0; i < 32; i += 8)
        t[ty + i][tx] = Wl[(size_t)(k0 + ty + i) * N + n0 + tx];
    __syncthreads();
    #pragma unroll
    for (int i = 0; i < 32; i += 8) {
        float v = t[tx][ty + i];
        size_t o = ob + (size_t)(n0 + ty + i) * K + k0 + tx;
        __nv_bfloat16 h = __float2bfloat16(v);
        Th[o] = h;
        Tl[o] = __float2bfloat16(v - __bfloat162float(h));
    }
}

// ======================= pipelined HMMA bf16 hi/lo GEMM =======================
// CTA 128x128, K-chunk 64, 2-stage cp.async double buffer (2 x 64KB smem).
#define AHI_OFF 0
#define ALO_OFF 16384
#define BHI_OFF 32768
#define BLO_OFF 49152
#define STAGE_SZ 65536
#define GEMM_SMEM (2*STAGE_SZ)

__device__ __forceinline__ void gemm_load_stage(
    uint32_t sb, int stg, int tid, int k0,
    const __nv_bfloat16* __restrict__ Ahi, const __nv_bfloat16* __restrict__ Alo, int lda,
    const __nv_bfloat16* __restrict__ Bhi, const __nv_bfloat16* __restrict__ Blo, int ldb,
    int m0, int n0) {
    uint32_t base = sb + stg * STAGE_SZ;
    #pragma unroll
    for (int p = 0; p < 4; ++p) {
        int lin = p * 256 + tid;
        int r = lin >> 3, kb = lin & 7;
        uint32_t soff = (uint32_t)(r * 128 + ((kb ^ (r & 7)) << 4));
        CP_ASYNC16(base + AHI_OFF + soff, Ahi + (size_t)(m0 + r) * lda + k0 + kb * 8);
        CP_ASYNC16(base + ALO_OFF + soff, Alo + (size_t)(m0 + r) * lda + k0 + kb * 8);
        CP_ASYNC16(base + BHI_OFF + soff, Bhi + (size_t)(n0 + r) * ldb + k0 + kb * 8);
        CP_ASYNC16(base + BLO_OFF + soff, Blo + (size_t)(n0 + r) * ldb + k0 + kb * 8);
    }
}

__global__ __launch_bounds__(256)
void hmma_gemm(const __nv_bfloat16* __restrict__ Ahi, const __nv_bfloat16* __restrict__ Alo, int lda,
               const __nv_bfloat16* __restrict__ Bhi, const __nv_bfloat16* __restrict__ Blo, int ldb,
               const float* __restrict__ bias, const float* __restrict__ resid,
               float* __restrict__ Cf, __nv_bfloat16* __restrict__ Chi, __nv_bfloat16* __restrict__ Clo,
               int ldc, int K, int gelu) {
    extern __shared__ char smem[];
    uint32_t sb = smem_u32(smem);
    int tid = threadIdx.x;
    int lane = tid & 31, wid = tid >> 5;
    int wm = wid >> 2, wn = wid & 3;
    int m0 = blockIdx.y * 128, n0 = blockIdx.x * 128;

    float acc[4][4][4];
    #pragma unroll
    for (int i = 0; i < 4; i++)
        #pragma unroll
        for (int j = 0; j < 4; j++)
            #pragma unroll
            for (int k = 0; k < 4; k++) acc[i][j][k] = 0.f;

    int a_row = (lane & 15);
    int a_kh  = (lane >> 4);
    int b_sub = (lane >> 3);
    int b_row = ((b_sub >> 1) << 3) + (lane & 7);
    int b_kh  = (b_sub & 1);

    const int nch = K >> 6;
    gemm_load_stage(sb, 0, tid, 0, Ahi, Alo, lda, Bhi, Blo, ldb, m0, n0);
    CP_COMMIT();

    for (int ch = 0; ch < nch; ++ch) {
        int cur = ch & 1;
        if (ch + 1 < nch) {
            gemm_load_stage(sb, cur ^ 1, tid, (ch + 1) << 6, Ahi, Alo, lda, Bhi, Blo, ldb, m0, n0);
            CP_COMMIT();
            CP_WAIT(1);
        } else {
            CP_WAIT(0);
        }
        __syncthreads();

        uint32_t stg = sb + cur * STAGE_SZ;
        #pragma unroll
        for (int ks = 0; ks < 4; ++ks) {
            uint32_t bh[4][2], bl[4][2];
            #pragma unroll
            for (int pair = 0; pair < 2; ++pair) {
                int row = wn * 32 + pair * 16 + b_row;
                int kb = ks * 2 + b_kh;
                uint32_t addr = stg + (uint32_t)(row * 128 + ((kb ^ (row & 7)) << 4));
                uint32_t rg[4];
                LDSM_X4(rg, addr + BHI_OFF);
                bh[pair * 2][0] = rg[0]; bh[pair * 2][1] = rg[1];
                bh[pair * 2 + 1][0] = rg[2]; bh[pair * 2 + 1][1] = rg[3];
                LDSM_X4(rg, addr + BLO_OFF);
                bl[pair * 2][0] = rg[0]; bl[pair * 2][1] = rg[1];
                bl[pair * 2 + 1][0] = rg[2]; bl[pair * 2 + 1][1] = rg[3];
            }
            #pragma unroll
            for (int mt = 0; mt < 4; ++mt) {
                int row = wm * 64 + mt * 16 + a_row;
                int kb = ks * 2 + a_kh;
                uint32_t addr = stg + (uint32_t)(row * 128 + ((kb ^ (row & 7)) << 4));
                uint32_t ah[4], al[4];
                LDSM_X4(ah, addr + AHI_OFF);
                LDSM_X4(al, addr + ALO_OFF);
                #pragma unroll
                for (int nt = 0; nt < 4; ++nt) {
                    MMA_BF16(acc[mt][nt], ah, bh[nt]);
                    MMA_BF16(acc[mt][nt], ah, bl[nt]);
                    MMA_BF16(acc[mt][nt], al, bh[nt]);
                }
            }
        }
        __syncthreads();
    }

    int rbase = m0 + wm * 64 + (lane >> 2);
    int cbase = n0 + wn * 32 + (lane & 3) * 2;
    #pragma unroll
    for (int mt = 0; mt < 4; ++mt) {
        #pragma unroll
        for (int nt = 0; nt < 4; ++nt) {
            #pragma unroll
            for (int half = 0; half < 2; ++half) {
                int gm = rbase + mt * 16 + half * 8;
                int gn = cbase + nt * 8;
                float v0 = acc[mt][nt][half * 2 + 0];
                float v1 = acc[mt][nt][half * 2 + 1];
                if (bias) { v0 += bias[gn]; v1 += bias[gn + 1]; }
                if (gelu) {
                    v0 = 0.5f * v0 * (1.0f + erff(v0 * 0.70710678118654752f));
                    v1 = 0.5f * v1 * (1.0f + erff(v1 * 0.70710678118654752f));
                }
                size_t go = (size_t)gm * ldc + gn;
                if (resid) { v0 += resid[go]; v1 += resid[go + 1]; }
                if (Cf) {
                    *reinterpret_cast<float2*>(Cf + go) = make_float2(v0, v1);
                } else {
                    __nv_bfloat16 h0 = __float2bfloat16(v0);
                    __nv_bfloat16 h1 = __float2bfloat16(v1);
                    __nv_bfloat162 hh2; hh2.x = h0; hh2.y = h1;
                    __nv_bfloat162 ll2;
                    ll2.x = __float2bfloat16(v0 - __bfloat162float(h0));
                    ll2.y = __float2bfloat16(v1 - __bfloat162float(h1));
                    *reinterpret_cast<__nv_bfloat162*>(Chi + go) = hh2;
                    *reinterpret_cast<__nv_bfloat162*>(Clo + go) = ll2;
                }
            }
        }
    }
}

// ======================= attention (fused qkv layout, ld=768) =======================
__global__ void summary_kernel(const float* __restrict__ qkv) {
    int u = blockIdx.x, bh = blockIdx.y;
    int b = bh >> 3, h = bh & 7;
    int e = threadIdx.x;
    const float* qp = qkv + ((size_t)(b * TT + u * BUCKET)) * QKVD + h * DH + e;
    const float* kp = qp + 256;
    float sq = 0.f, sk = 0.f;
    #pragma unroll 8
    for (int i = 0; i < BUCKET; i++) {
        sq += qp[(size_t)i * QKVD];
        sk += kp[(size_t)i * QKVD];
    }
    g_sq[((size_t)bh * NB + u) * DH + e] = sq * (1.0f / BUCKET);
    g_sk[((size_t)bh * NB + u) * DH + e] = sk * (1.0f / BUCKET);
}

__global__ void routing_kernel() {
    int bh = blockIdx.x;
    int i = threadIdx.x;
    __shared__ float ssk[NB][DH];
    const float* base = g_sk + (size_t)bh * NB * DH;
    for (int idx = i; idx < NB * DH; idx += NB) ssk[idx / DH][idx % DH] = base[idx];
    float sq[DH];
    const float* sqp = g_sq + ((size_t)bh * NB + i) * DH;
    #pragma unroll
    for (int e = 0; e < DH; e++) sq[e] = sqp[e];
    __syncthreads();
    const float sc = 0.17677669529663687f * (1.0f / 0.75f);
    float mx = -1e30f; int am = 0;
    for (int j = 0; j < NB; j++) {
        float d = 0.f;
        #pragma unroll
        for (int e = 0; e < DH; e++) d = fmaf(sq[e], ssk[j][e], d);
        d *= sc;
        if (d > mx) { mx = d; am = j; }
    }
    float sum = 0.f;
    for (int j = 0; j < NB; j++) {
        float d = 0.f;
        #pragma unroll
        for (int e = 0; e < DH; e++) d = fmaf(sq[e], ssk[j][e], d);
        sum += expf(d * sc - mx);
    }
    g_top[bh * NB + i] = 1.0f / sum;
    g_idx[bh * NB + i] = am;
}

__global__ void attn_kernel(const float* __restrict__ qkv,
                            __nv_bfloat16* __restrict__ ohi, __nv_bfloat16* __restrict__ olo) {
    int u = blockIdx.x, bh = blockIdx.y;
    int b = bh >> 3, h = bh & 7;
    __shared__ float sQ[64][DH];
    __shared__ float sK[128][DH + 1];
    __shared__ float sV[128][DH];
    __shared__ float sP[8][128];
    int tid = threadIdx.x;
    int warp = tid >> 5, lane = tid & 31;
    float top = g_top[bh * NB + u];
    int ridx = g_idx[bh * NB + u];
    const float* qbase = qkv + ((size_t)(b * TT + u * BUCKET)) * QKVD + h * DH;
    const float* kself = qbase + 256;
    const float* krout = qkv + ((size_t)(b * TT + ridx * BUCKET)) * QKVD + 256 + h * DH;
    for (int i = tid; i < 64 * DH; i += 256) {
        int r = i >> 5, e = i & 31;
        sQ[r][e]      = qbase[(size_t)r * QKVD + e];
        sK[r][e]      = top * krout[(size_t)r * QKVD + e];
        sV[r][e]      = top * krout[(size_t)r * QKVD + 256 + e];
        sK[64 + r][e] =       kself[(size_t)r * QKVD + e];
        sV[64 + r][e] =       kself[(size_t)r * QKVD + 256 + e];
    }
    __syncthreads();
    const float scale = 0.17677669529663687f;
    size_t obase = ((size_t)(b * TT + u * BUCKET)) * DIMM + h * DH;
    for (int rr = 0; rr < 8; rr++) {
        int r = warp * 8 + rr;
        float d[4];
        #pragma unroll
        for (int c = 0; c < 4; c++) {
            int j = lane + c * 32;
            float a = 0.f;
            #pragma unroll
            for (int e = 0; e < DH; e++) a = fmaf(sQ[r][e], sK[j][e], a);
            d[c] = a * scale;
        }
        float mx = fmaxf(fmaxf(d[0], d[1]), fmaxf(d[2], d[3]));
        #pragma unroll
        for (int off = 16; off; off >>= 1) mx = fmaxf(mx, __shfl_xor_sync(0xffffffffu, mx, off));
        float p[4], s = 0.f;
        #pragma unroll
        for (int c = 0; c < 4; c++) { p[c] = __expf(d[c] - mx); s += p[c]; }
        #pragma unroll
        for (int off = 16; off; off >>= 1) s += __shfl_xor_sync(0xffffffffu, s, off);
        float inv = 1.0f / s;
        #pragma unroll
        for (int c = 0; c < 4; c++) sP[warp][lane + c * 32] = p[c] * inv;
        __syncwarp();
        float a = 0.f;
        #pragma unroll
        for (int j = 0; j < 128; j++) a = fmaf(sP[warp][j], sV[j][lane], a);
        __nv_bfloat16 hb = __float2bfloat16(a);
        ohi[obase + (size_t)r * DIMM + lane] = hb;
        olo[obase + (size_t)r * DIMM + lane] = __float2bfloat16(a - __bfloat162float(hb));
        __syncwarp();
    }
}

// ======================= host orchestration =======================
extern "C" void kernel_launch(void* const* d_in, const int* in_sizes, int n_in,
                              void* d_out, int out_size) {
    const float* x     = (const float*)d_in[0];
    const float* pe0   = (const float*)d_in[1];
    const float* pe1   = (const float*)d_in[2];
    const float* ln1_g = (const float*)d_in[3];
    const float* ln1_b = (const float*)d_in[4];
    const float* Wq    = (const float*)d_in[5];
    const float* Wkv   = (const float*)d_in[6];
    const float* Wo    = (const float*)d_in[7];
    const float* bo    = (const float*)d_in[8];
    const float* ln2_g = (const float*)d_in[9];
    const float* ln2_b = (const float*)d_in[10];
    const float* W1    = (const float*)d_in[11];
    const float* b1    = (const float*)d_in[12];
    const float* W2    = (const float*)d_in[13];
    const float* b2    = (const float*)d_in[14];
    const float* gf    = (const float*)d_in[15];
    const float* bf    = (const float*)d_in[16];
    float* out = (float*)d_out;

    cudaFuncSetAttribute(hmma_gemm, cudaFuncAttributeMaxDynamicSharedMemorySize, GEMM_SMEM);

    float *y, *qkv;
    __nv_bfloat16 *hh, *hl, *ohi, *olo, *ffh, *ffl;
    __nv_bfloat16 *wqkvh, *wqkvl, *woh, *wol, *w1h, *w1l, *w2h, *w2l;
    cudaGetSymbolAddress((void**)&y, g_y);
    cudaGetSymbolAddress((void**)&qkv, g_qkv);
    cudaGetSymbolAddress((void**)&hh, g_hh);   cudaGetSymbolAddress((void**)&hl, g_hl);
    cudaGetSymbolAddress((void**)&ohi, g_ohi); cudaGetSymbolAddress((void**)&olo, g_olo);
    cudaGetSymbolAddress((void**)&ffh, g_ffh); cudaGetSymbolAddress((void**)&ffl, g_ffl);
    cudaGetSymbolAddress((void**)&wqkvh, g_wqkvh); cudaGetSymbolAddress((void**)&wqkvl, g_wqkvl);
    cudaGetSymbolAddress((void**)&woh, g_woh);     cudaGetSymbolAddress((void**)&wol, g_wol);
    cudaGetSymbolAddress((void**)&w1h, g_w1h);     cudaGetSymbolAddress((void**)&w1l, g_w1l);
    cudaGetSymbolAddress((void**)&w2h, g_w2h);     cudaGetSymbolAddress((void**)&w2l, g_w2l);

    dim3 tb(32, 8);
    const size_t QKV_LS = (size_t)QKVD * DIMM;
    // pack q rows [0,256), kv rows [256,768) of the fused (768,256) transposed weight
    wconv_kernel<<<dim3(DIMM / 32,   DIMM / 32, DEPTHN), tb>>>(Wq,  wqkvh, wqkvl, DIMM, DIMM, QKV_LS);
    wconv_kernel<<<dim3(2*DIMM / 32, DIMM / 32, DEPTHN), tb>>>(Wkv, wqkvh + 256 * DIMM, wqkvl + 256 * DIMM, DIMM, 2*DIMM, QKV_LS);
    wconv_kernel<<<dim3(DIMM / 32,   DIMM / 32, DEPTHN), tb>>>(Wo,  woh, wol, DIMM, DIMM, (size_t)DIMM * DIMM);
    wconv_kernel<<<dim3(FFD / 32,    DIMM / 32, DEPTHN), tb>>>(W1,  w1h, w1l, DIMM, FFD, (size_t)DIMM * FFD);
    wconv_kernel<<<dim3(DIMM / 32,   FFD / 32,  DEPTHN), tb>>>(W2,  w2h, w2l, FFD,  DIMM, (size_t)DIMM * FFD);

    dim3 tg(TT / 32, DIMM / 32, BB);
    pos_add_kernel<<<tg, tb>>>(x, pe0, pe1, y);

    for (int L = 0; L < DEPTHN; L++) {
        const float* bo_ = bo + (size_t)L * DIMM;
        const float* bb1 = b1 + (size_t)L * FFD;
        const float* bb2 = b2 + (size_t)L * DIMM;
        size_t oqkv = (size_t)L * QKV_LS;
        size_t oo   = (size_t)L * DIMM * DIMM;
        size_t off1 = (size_t)L * DIMM * FFD;

        ln_pair_kernel<<<MROWS / 8, 256>>>(y, hh, hl, ln1_g + (size_t)L * DIMM, ln1_b + (size_t)L * DIMM);
        hmma_gemm<<<dim3(QKVD / 128, MROWS / 128), 256, GEMM_SMEM>>>(hh, hl, DIMM,
            wqkvh + oqkv, wqkvl + oqkv, DIMM,
            nullptr, nullptr, qkv, nullptr, nullptr, QKVD, DIMM, 0);
        summary_kernel<<<dim3(NB, BHN), DH>>>(qkv);
        routing_kernel<<<BHN, NB>>>();
        attn_kernel<<<dim3(NB, BHN), 256>>>(qkv, ohi, olo);
        hmma_gemm<<<dim3(2, MROWS / 128), 256, GEMM_SMEM>>>(ohi, olo, DIMM, woh + oo, wol + oo, DIMM,
            bo_, y, y, nullptr, nullptr, DIMM, DIMM, 0);
        ln_pair_kernel<<<MROWS / 8, 256>>>(y, hh, hl, ln2_g + (size_t)L * DIMM, ln2_b + (size_t)L * DIMM);
        hmma_gemm<<<dim3(8, MROWS / 128), 256, GEMM_SMEM>>>(hh, hl, DIMM, w1h + off1, w1l + off1, DIMM,
            bb1, nullptr, nullptr, ffh, ffl, FFD, DIMM, 1);
        hmma_gemm<<<dim3(2, MROWS / 128), 256, GEMM_SMEM>>>(ffh, ffl, FFD, w2h + off1, w2l + off1, FFD,
            bb2, y, y, nullptr, nullptr, DIMM, FFD, 0);
    }

    ln_kernel<<<MROWS / 8, 256>>>(y, qkv, gf, bf);   // reuse qkv as scratch
    out_transpose_kernel<<<tg, tb>>>(qkv, out);
    (void)in_sizes; (void)n_in; (void)out_size;
}

// round 5
// speedup vs baseline: 2.8812x; 1.1461x over previous
#include <cuda_runtime.h>
#include <cuda_fp16.h>
#include <math.h>
#include <cstdint>

#define DIMM   256
#define TT     8192
#define BB     4
#define HEADSN 8
#define DH     32
#define NB     128
#define BUCKET 64
#define FFD    1024
#define DEPTHN 6
#define MROWS  (BB*TT)
#define BHN    (BB*HEADSN)
#define QKVD   768
#define NBK    (BB*NB)      // 512 buckets total

// ======================= static device scratch =======================
__device__ float g_y  [MROWS*DIMM];
__device__ float g_qkv[MROWS*QKVD];
__device__ __half g_h [MROWS*DIMM];
__device__ __half g_o [MROWS*DIMM];
__device__ __half g_ff[MROWS*FFD];
__device__ __half g_wqkvh[DEPTHN*QKVD*DIMM], g_wqkvl[DEPTHN*QKVD*DIMM];
__device__ __half g_woh [DEPTHN*DIMM*DIMM],  g_wol [DEPTHN*DIMM*DIMM];
__device__ __half g_w1h [DEPTHN*DIMM*FFD],   g_w1l [DEPTHN*DIMM*FFD];
__device__ __half g_w2h [DEPTHN*FFD*DIMM],   g_w2l [DEPTHN*FFD*DIMM];
__device__ float g_hmean[NBK*DIMM];
__device__ float g_sq[BHN*NB*DH];
__device__ float g_sk[BHN*NB*DH];
__device__ float g_top[BHN*NB];
__device__ int   g_idx[BHN*NB];

// ======================= helpers =======================
__device__ __forceinline__ uint32_t smem_u32(const void* p) {
    uint32_t a;
    asm("{ .reg .u64 t; cvta.to.shared.u64 t, %1; cvt.u32.u64 %0, t; }" : "=r"(a) : "l"(p));
    return a;
}

#define MMA_F16(c, a, b) \
    asm volatile("mma.sync.aligned.m16n8k16.row.col.f32.f16.f16.f32 " \
        "{%0,%1,%2,%3}, {%4,%5,%6,%7}, {%8,%9}, {%0,%1,%2,%3};" \
        : "+f"((c)[0]), "+f"((c)[1]), "+f"((c)[2]), "+f"((c)[3]) \
        : "r"((a)[0]), "r"((a)[1]), "r"((a)[2]), "r"((a)[3]), "r"((b)[0]), "r"((b)[1]))

#define LDSM_X4(r, addr) \
    asm volatile("ldmatrix.sync.aligned.m8n8.x4.shared.b16 {%0,%1,%2,%3}, [%4];" \
        : "=r"((r)[0]), "=r"((r)[1]), "=r"((r)[2]), "=r"((r)[3]) : "r"(addr))

#define CP_ASYNC16(dst, src) \
    asm volatile("cp.async.cg.shared.global [%0], [%1], 16;" :: "r"(dst), "l"(src))
#define CP_COMMIT()  asm volatile("cp.async.commit_group;" ::: "memory")
#define CP_WAIT(n)   asm volatile("cp.async.wait_group %0;" :: "n"(n) : "memory")

// ======================= small kernels =======================
__global__ void pos_add_kernel(const float* __restrict__ x, const float* __restrict__ pe0,
                               const float* __restrict__ pe1, float* __restrict__ y) {
    __shared__ float tile[32][33];
    int b = blockIdx.z, d0 = blockIdx.y * 32, t0 = blockIdx.x * 32;
    int tx = threadIdx.x, ty = threadIdx.y;
    const float* xb = x + (size_t)b * DIMM * TT;
    #pragma unroll
    for (int i = 0; i < 32; i += 8)
        tile[ty + i][tx] = xb[(size_t)(d0 + ty + i) * TT + t0 + tx];
    __syncthreads();
    float* yb = y + (size_t)b * TT * DIMM;
    #pragma unroll
    for (int i = 0; i < 32; i += 8) {
        int t = t0 + ty + i, d = d0 + tx;
        yb[(size_t)t * DIMM + d] =
            tile[tx][ty + i] + pe0[(size_t)(t >> 6) * DIMM + d] + pe1[(size_t)(t & 63) * DIMM + d];
    }
}

__global__ void out_transpose_kernel(const float* __restrict__ hin, float* __restrict__ out) {
    __shared__ float tile[32][33];
    int b = blockIdx.z, d0 = blockIdx.y * 32, t0 = blockIdx.x * 32;
    int tx = threadIdx.x, ty = threadIdx.y;
    const float* hb = hin + (size_t)b * TT * DIMM;
    #pragma unroll
    for (int i = 0; i < 32; i += 8)
        tile[ty + i][tx] = hb[(size_t)(t0 + ty + i) * DIMM + d0 + tx];
    __syncthreads();
    float* ob = out + (size_t)b * DIMM * TT;
    #pragma unroll
    for (int i = 0; i < 32; i += 8)
        ob[(size_t)(d0 + ty + i) * TT + t0 + tx] = tile[tx][ty + i];
}

// LN -> fp32 (final)
__global__ void ln_kernel(const float* __restrict__ in, float* __restrict__ out,
                          const float* __restrict__ g, const float* __restrict__ b) {
    int row = blockIdx.x * 8 + (threadIdx.x >> 5);
    int lane = threadIdx.x & 31;
    const float* r = in + (size_t)row * DIMM;
    float v[8], s = 0.f;
    #pragma unroll
    for (int i = 0; i < 8; i++) { v[i] = r[lane + i * 32]; s += v[i]; }
    #pragma unroll
    for (int off = 16; off; off >>= 1) s += __shfl_xor_sync(0xffffffffu, s, off);
    float m = s * (1.0f / DIMM), var = 0.f;
    #pragma unroll
    for (int i = 0; i < 8; i++) { float d = v[i] - m; var += d * d; }
    #pragma unroll
    for (int off = 16; off; off >>= 1) var += __shfl_xor_sync(0xffffffffu, var, off);
    float inv = rsqrtf(var * (1.0f / DIMM) + 1e-5f);
    float* o = out + (size_t)row * DIMM;
    #pragma unroll
    for (int i = 0; i < 8; i++) {
        int c = lane + i * 32;
        o[c] = (v[i] - m) * inv * g[c] + b[c];
    }
}

// LN -> fp16 (GEMM A operand)
__global__ void ln_h_kernel(const float* __restrict__ in, __half* __restrict__ oh,
                            const float* __restrict__ g, const float* __restrict__ b) {
    int row = blockIdx.x * 8 + (threadIdx.x >> 5);
    int lane = threadIdx.x & 31;
    const float* r = in + (size_t)row * DIMM;
    float v[8], s = 0.f;
    #pragma unroll
    for (int i = 0; i < 8; i++) { v[i] = r[lane + i * 32]; s += v[i]; }
    #pragma unroll
    for (int off = 16; off; off >>= 1) s += __shfl_xor_sync(0xffffffffu, s, off);
    float m = s * (1.0f / DIMM), var = 0.f;
    #pragma unroll
    for (int i = 0; i < 8; i++) { float d = v[i] - m; var += d * d; }
    #pragma unroll
    for (int off = 16; off; off >>= 1) var += __shfl_xor_sync(0xffffffffu, var, off);
    float inv = rsqrtf(var * (1.0f / DIMM) + 1e-5f);
    #pragma unroll
    for (int i = 0; i < 8; i++) {
        int c = lane + i * 32;
        oh[(size_t)row * DIMM + c] = __float2half((v[i] - m) * inv * g[c] + b[c]);
    }
}

// fp32 bucket means of LN(y): hmean[bucket][c] (exact routing path)
__global__ void bucket_ln_mean_kernel(const float* __restrict__ y,
                                      const float* __restrict__ g, const float* __restrict__ b,
                                      float* __restrict__ hmean) {
    __shared__ float acc[8][DIMM];
    int bu = blockIdx.x;                 // 0..NBK-1
    int warp = threadIdx.x >> 5, lane = threadIdx.x & 31;
    #pragma unroll
    for (int i = 0; i < 8; i++) acc[warp][lane + i * 32] = 0.f;
    __syncthreads();
    for (int rr = 0; rr < 8; rr++) {
        int row = bu * BUCKET + warp * 8 + rr;
        const float* r = y + (size_t)row * DIMM;
        float v[8], s = 0.f;
        #pragma unroll
        for (int i = 0; i < 8; i++) { v[i] = r[lane + i * 32]; s += v[i]; }
        #pragma unroll
        for (int off = 16; off; off >>= 1) s += __shfl_xor_sync(0xffffffffu, s, off);
        float m = s * (1.0f / DIMM), var = 0.f;
        #pragma unroll
        for (int i = 0; i < 8; i++) { float d = v[i] - m; var += d * d; }
        #pragma unroll
        for (int off = 16; off; off >>= 1) var += __shfl_xor_sync(0xffffffffu, var, off);
        float inv = rsqrtf(var * (1.0f / DIMM) + 1e-5f);
        #pragma unroll
        for (int i = 0; i < 8; i++) {
            int c = lane + i * 32;
            acc[warp][c] += (v[i] - m) * inv * g[c] + b[c];
        }
    }
    __syncthreads();
    // reduce 8 -> 1
    for (int c = threadIdx.x; c < DIMM; c += 256) {
        float s = 0.f;
        #pragma unroll
        for (int w = 0; w < 8; w++) s += acc[w][c];
        hmean[(size_t)bu * DIMM + c] = s * (1.0f / BUCKET);
    }
}

// small fp32 gemm: sq/sk = hmean @ Wq / Wkv[:, :256]  (exact routing)
__global__ void route_gemm_kernel(const float* __restrict__ hmean,
                                  const float* __restrict__ Wq, const float* __restrict__ Wkv) {
    __shared__ float hm[DIMM];
    int row = blockIdx.x;                // 0..NBK-1   (= b*NB + u)
    int sel = blockIdx.y;                // 0 = q, 1 = k
    int c = threadIdx.x;                 // 0..255
    hm[c] = hmean[(size_t)row * DIMM + c];
    __syncthreads();
    const float* W = sel ? Wkv : Wq;
    int ldw = sel ? 2 * DIMM : DIMM;
    float a = 0.f;
    #pragma unroll 8
    for (int k = 0; k < DIMM; k++) a = fmaf(hm[k], W[(size_t)k * ldw + c], a);
    int b = row >> 7, u = row & 127;
    int h = c >> 5, e = c & 31;
    size_t dst = (((size_t)(b * HEADSN + h)) * NB + u) * DH + e;
    if (sel) g_sk[dst] = a; else g_sq[dst] = a;
}

// W (K,N) fp32 -> WT (N,K) fp16 hi/lo
__global__ void wconv_kernel(const float* __restrict__ W, __half* __restrict__ Th,
                             __half* __restrict__ Tl, int K, int N, size_t lstride) {
    __shared__ float t[32][33];
    int l = blockIdx.z;
    const float* Wl = W + (size_t)l * K * N;
    size_t ob = (size_t)l * lstride;
    int n0 = blockIdx.x * 32, k0 = blockIdx.y * 32;
    int tx = threadIdx.x, ty = threadIdx.y;
    #pragma unroll
    for (int i = 0; i < 32; i += 8)
        t[ty + i][tx] = Wl[(size_t)(k0 + ty + i) * N + n0 + tx];
    __syncthreads();
    #pragma unroll
    for (int i = 0; i < 32; i += 8) {
        float v = t[tx][ty + i];
        size_t o = ob + (size_t)(n0 + ty + i) * K + k0 + tx;
        __half h = __float2half(v);
        Th[o] = h;
        Tl[o] = __float2half(v - __half2float(h));
    }
}

// ======================= pipelined fp16 2-term HMMA GEMM =======================
// C = Ah(M,K) @ (Bh+Bl)^T(N,K). CTA 128x128, K-chunk 64, 3-stage cp.async.
#define AH_OFF 0
#define BH_OFF 16384
#define BL_OFF 32768
#define STAGE_SZ 49152
#define NSTAGE 3
#define GEMM_SMEM (NSTAGE*STAGE_SZ)

__device__ __forceinline__ void gemm_load_stage(
    uint32_t sb, int stg, int tid, int k0,
    const __half* __restrict__ Ah, int lda,
    const __half* __restrict__ Bh, const __half* __restrict__ Bl, int ldb,
    int m0, int n0) {
    uint32_t base = sb + stg * STAGE_SZ;
    #pragma unroll
    for (int p = 0; p < 4; ++p) {
        int lin = p * 256 + tid;
        int r = lin >> 3, kb = lin & 7;
        uint32_t soff = (uint32_t)(r * 128 + ((kb ^ (r & 7)) << 4));
        CP_ASYNC16(base + AH_OFF + soff, Ah + (size_t)(m0 + r) * lda + k0 + kb * 8);
        CP_ASYNC16(base + BH_OFF + soff, Bh + (size_t)(n0 + r) * ldb + k0 + kb * 8);
        CP_ASYNC16(base + BL_OFF + soff, Bl + (size_t)(n0 + r) * ldb + k0 + kb * 8);
    }
}

__global__ __launch_bounds__(256)
void hmma_gemm(const __half* __restrict__ Ah, int lda,
               const __half* __restrict__ Bh, const __half* __restrict__ Bl, int ldb,
               const float* __restrict__ bias, const float* __restrict__ resid,
               float* __restrict__ Cf, __half* __restrict__ Ch,
               int ldc, int K, int gelu) {
    extern __shared__ char smem[];
    uint32_t sb = smem_u32(smem);
    int tid = threadIdx.x;
    int lane = tid & 31, wid = tid >> 5;
    int wm = wid >> 2, wn = wid & 3;
    int m0 = blockIdx.y * 128, n0 = blockIdx.x * 128;

    float acc[4][4][4];
    #pragma unroll
    for (int i = 0; i < 4; i++)
        #pragma unroll
        for (int j = 0; j < 4; j++)
            #pragma unroll
            for (int k = 0; k < 4; k++) acc[i][j][k] = 0.f;

    int a_row = (lane & 15);
    int a_kh  = (lane >> 4);
    int b_sub = (lane >> 3);
    int b_row = ((b_sub >> 1) << 3) + (lane & 7);
    int b_kh  = (b_sub & 1);

    const int nch = K >> 6;
    gemm_load_stage(sb, 0, tid, 0, Ah, lda, Bh, Bl, ldb, m0, n0);
    CP_COMMIT();
    if (nch > 1) {
        gemm_load_stage(sb, 1, tid, 64, Ah, lda, Bh, Bl, ldb, m0, n0);
        CP_COMMIT();
    }

    for (int ch = 0; ch < nch; ++ch) {
        if (ch + 2 < nch) {
            gemm_load_stage(sb, (ch + 2) % NSTAGE, tid, (ch + 2) << 6, Ah, lda, Bh, Bl, ldb, m0, n0);
            CP_COMMIT();
            CP_WAIT(2);
        } else if (ch + 1 < nch) {
            CP_WAIT(1);
        } else {
            CP_WAIT(0);
        }
        __syncthreads();

        uint32_t stg = sb + (ch % NSTAGE) * STAGE_SZ;
        #pragma unroll
        for (int ks = 0; ks < 4; ++ks) {
            uint32_t bh[4][2], bl[4][2];
            #pragma unroll
            for (int pair = 0; pair < 2; ++pair) {
                int row = wn * 32 + pair * 16 + b_row;
                int kb = ks * 2 + b_kh;
                uint32_t addr = stg + (uint32_t)(row * 128 + ((kb ^ (row & 7)) << 4));
                uint32_t rg[4];
                LDSM_X4(rg, addr + BH_OFF);
                bh[pair * 2][0] = rg[0]; bh[pair * 2][1] = rg[1];
                bh[pair * 2 + 1][0] = rg[2]; bh[pair * 2 + 1][1] = rg[3];
                LDSM_X4(rg, addr + BL_OFF);
                bl[pair * 2][0] = rg[0]; bl[pair * 2][1] = rg[1];
                bl[pair * 2 + 1][0] = rg[2]; bl[pair * 2 + 1][1] = rg[3];
            }
            #pragma unroll
            for (int mt = 0; mt < 4; ++mt) {
                int row = wm * 64 + mt * 16 + a_row;
                int kb = ks * 2 + a_kh;
                uint32_t addr = stg + (uint32_t)(row * 128 + ((kb ^ (row & 7)) << 4));
                uint32_t ah[4];
                LDSM_X4(ah, addr + AH_OFF);
                #pragma unroll
                for (int nt = 0; nt < 4; ++nt) {
                    MMA_F16(acc[mt][nt], ah, bh[nt]);
                    MMA_F16(acc[mt][nt], ah, bl[nt]);
                }
            }
        }
        __syncthreads();
    }

    int rbase = m0 + wm * 64 + (lane >> 2);
    int cbase = n0 + wn * 32 + (lane & 3) * 2;
    #pragma unroll
    for (int mt = 0; mt < 4; ++mt) {
        #pragma unroll
        for (int nt = 0; nt < 4; ++nt) {
            #pragma unroll
            for (int half = 0; half < 2; ++half) {
                int gm = rbase + mt * 16 + half * 8;
                int gn = cbase + nt * 8;
                float v0 = acc[mt][nt][half * 2 + 0];
                float v1 = acc[mt][nt][half * 2 + 1];
                if (bias) { v0 += bias[gn]; v1 += bias[gn + 1]; }
                if (gelu) {
                    v0 = 0.5f * v0 * (1.0f + erff(v0 * 0.70710678118654752f));
                    v1 = 0.5f * v1 * (1.0f + erff(v1 * 0.70710678118654752f));
                }
                size_t go = (size_t)gm * ldc + gn;
                if (resid) { v0 += resid[go]; v1 += resid[go + 1]; }
                if (Cf) {
                    *reinterpret_cast<float2*>(Cf + go) = make_float2(v0, v1);
                } else {
                    *reinterpret_cast<__half2*>(Ch + go) = __floats2half2_rn(v0, v1);
                }
            }
        }
    }
}

// ======================= attention =======================
__global__ void routing_kernel() {
    int bh = blockIdx.x;
    int i = threadIdx.x;
    __shared__ float ssk[NB][DH];
    const float* base = g_sk + (size_t)bh * NB * DH;
    for (int idx = i; idx < NB * DH; idx += NB) ssk[idx / DH][idx % DH] = base[idx];
    float sq[DH];
    const float* sqp = g_sq + ((size_t)bh * NB + i) * DH;
    #pragma unroll
    for (int e = 0; e < DH; e++) sq[e] = sqp[e];
    __syncthreads();
    const float sc = 0.17677669529663687f * (1.0f / 0.75f);
    float mx = -1e30f; int am = 0;
    for (int j = 0; j < NB; j++) {
        float d = 0.f;
        #pragma unroll
        for (int e = 0; e < DH; e++) d = fmaf(sq[e], ssk[j][e], d);
        d *= sc;
        if (d > mx) { mx = d; am = j; }
    }
    float sum = 0.f;
    for (int j = 0; j < NB; j++) {
        float d = 0.f;
        #pragma unroll
        for (int e = 0; e < DH; e++) d = fmaf(sq[e], ssk[j][e], d);
        sum += expf(d * sc - mx);
    }
    g_top[bh * NB + i] = 1.0f / sum;
    g_idx[bh * NB + i] = am;
}

__global__ void attn_kernel(const float* __restrict__ qkv, __half* __restrict__ o) {
    int u = blockIdx.x, bh = blockIdx.y;
    int b = bh >> 3, h = bh & 7;
    __shared__ float sQ[64][DH];
    __shared__ float sK[128][DH + 1];
    __shared__ float sV[128][DH];
    __shared__ float sP[8][128];
    int tid = threadIdx.x;
    int warp = tid >> 5, lane = tid & 31;
    float top = g_top[bh * NB + u];
    int ridx = g_idx[bh * NB + u];
    const float* qbase = qkv + ((size_t)(b * TT + u * BUCKET)) * QKVD + h * DH;
    const float* kself = qbase + 256;
    const float* krout = qkv + ((size_t)(b * TT + ridx * BUCKET)) * QKVD + 256 + h * DH;
    for (int i = tid; i < 64 * DH; i += 256) {
        int r = i >> 5, e = i & 31;
        sQ[r][e]      = qbase[(size_t)r * QKVD + e];
        sK[r][e]      = top * krout[(size_t)r * QKVD + e];
        sV[r][e]      = top * krout[(size_t)r * QKVD + 256 + e];
        sK[64 + r][e] =       kself[(size_t)r * QKVD + e];
        sV[64 + r][e] =       kself[(size_t)r * QKVD + 256 + e];
    }
    __syncthreads();
    const float scale = 0.17677669529663687f;
    size_t obase = ((size_t)(b * TT + u * BUCKET)) * DIMM + h * DH;
    for (int rr = 0; rr < 8; rr++) {
        int r = warp * 8 + rr;
        float d[4];
        #pragma unroll
        for (int c = 0; c < 4; c++) {
            int j = lane + c * 32;
            float a = 0.f;
            #pragma unroll
            for (int e = 0; e < DH; e++) a = fmaf(sQ[r][e], sK[j][e], a);
            d[c] = a * scale;
        }
        float mx = fmaxf(fmaxf(d[0], d[1]), fmaxf(d[2], d[3]));
        #pragma unroll
        for (int off = 16; off; off >>= 1) mx = fmaxf(mx, __shfl_xor_sync(0xffffffffu, mx, off));
        float p[4], s = 0.f;
        #pragma unroll
        for (int c = 0; c < 4; c++) { p[c] = __expf(d[c] - mx); s += p[c]; }
        #pragma unroll
        for (int off = 16; off; off >>= 1) s += __shfl_xor_sync(0xffffffffu, s, off);
        float inv = 1.0f / s;
        #pragma unroll
        for (int c = 0; c < 4; c++) sP[warp][lane + c * 32] = p[c] * inv;
        __syncwarp();
        float a = 0.f;
        #pragma unroll
        for (int j = 0; j < 128; j++) a = fmaf(sP[warp][j], sV[j][lane], a);
        o[obase + (size_t)r * DIMM + lane] = __float2half(a);
        __syncwarp();
    }
}

// ======================= host orchestration =======================
extern "C" void kernel_launch(void* const* d_in, const int* in_sizes, int n_in,
                              void* d_out, int out_size) {
    const float* x     = (const float*)d_in[0];
    const float* pe0   = (const float*)d_in[1];
    const float* pe1   = (const float*)d_in[2];
    const float* ln1_g = (const float*)d_in[3];
    const float* ln1_b = (const float*)d_in[4];
    const float* Wq    = (const float*)d_in[5];
    const float* Wkv   = (const float*)d_in[6];
    const float* Wo    = (const float*)d_in[7];
    const float* bo    = (const float*)d_in[8];
    const float* ln2_g = (const float*)d_in[9];
    const float* ln2_b = (const float*)d_in[10];
    const float* W1    = (const float*)d_in[11];
    const float* b1    = (const float*)d_in[12];
    const float* W2    = (const float*)d_in[13];
    const float* b2    = (const float*)d_in[14];
    const float* gf    = (const float*)d_in[15];
    const float* bf    = (const float*)d_in[16];
    float* out = (float*)d_out;

    cudaFuncSetAttribute(hmma_gemm, cudaFuncAttributeMaxDynamicSharedMemorySize, GEMM_SMEM);

    float *y, *qkv, *hmean;
    __half *h, *o, *ff;
    __half *wqkvh, *wqkvl, *woh, *wol, *w1h, *w1l, *w2h, *w2l;
    cudaGetSymbolAddress((void**)&y, g_y);
    cudaGetSymbolAddress((void**)&qkv, g_qkv);
    cudaGetSymbolAddress((void**)&hmean, g_hmean);
    cudaGetSymbolAddress((void**)&h, g_h);
    cudaGetSymbolAddress((void**)&o, g_o);
    cudaGetSymbolAddress((void**)&ff, g_ff);
    cudaGetSymbolAddress((void**)&wqkvh, g_wqkvh); cudaGetSymbolAddress((void**)&wqkvl, g_wqkvl);
    cudaGetSymbolAddress((void**)&woh, g_woh);     cudaGetSymbolAddress((void**)&wol, g_wol);
    cudaGetSymbolAddress((void**)&w1h, g_w1h);     cudaGetSymbolAddress((void**)&w1l, g_w1l);
    cudaGetSymbolAddress((void**)&w2h, g_w2h);     cudaGetSymbolAddress((void**)&w2l, g_w2l);

    dim3 tb(32, 8);
    const size_t QKV_LS = (size_t)QKVD * DIMM;
    wconv_kernel<<<dim3(DIMM / 32,   DIMM / 32, DEPTHN), tb>>>(Wq,  wqkvh, wqkvl, DIMM, DIMM, QKV_LS);
    wconv_kernel<<<dim3(2*DIMM / 32, DIMM / 32, DEPTHN), tb>>>(Wkv, wqkvh + 256 * DIMM, wqkvl + 256 * DIMM, DIMM, 2*DIMM, QKV_LS);
    wconv_kernel<<<dim3(DIMM / 32,   DIMM / 32, DEPTHN), tb>>>(Wo,  woh, wol, DIMM, DIMM, (size_t)DIMM * DIMM);
    wconv_kernel<<<dim3(FFD / 32,    DIMM / 32, DEPTHN), tb>>>(W1,  w1h, w1l, DIMM, FFD, (size_t)DIMM * FFD);
    wconv_kernel<<<dim3(DIMM / 32,   FFD / 32,  DEPTHN), tb>>>(W2,  w2h, w2l, FFD,  DIMM, (size_t)DIMM * FFD);

    dim3 tg(TT / 32, DIMM / 32, BB);
    pos_add_kernel<<<tg, tb>>>(x, pe0, pe1, y);

    for (int L = 0; L < DEPTHN; L++) {
        const float* g1 = ln1_g + (size_t)L * DIMM;
        const float* bb = ln1_b + (size_t)L * DIMM;
        const float* bo_ = bo + (size_t)L * DIMM;
        const float* bb1 = b1 + (size_t)L * FFD;
        const float* bb2 = b2 + (size_t)L * DIMM;
        size_t oqkv = (size_t)L * QKV_LS;
        size_t oo   = (size_t)L * DIMM * DIMM;
        size_t off1 = (size_t)L * DIMM * FFD;

        ln_h_kernel<<<MROWS / 8, 256>>>(y, h, g1, bb);
        hmma_gemm<<<dim3(QKVD / 128, MROWS / 128), 256, GEMM_SMEM>>>(h, DIMM,
            wqkvh + oqkv, wqkvl + oqkv, DIMM,
            nullptr, nullptr, qkv, nullptr, QKVD, DIMM, 0);
        // exact fp32 routing path
        bucket_ln_mean_kernel<<<NBK, 256>>>(y, g1, bb, hmean);
        route_gemm_kernel<<<dim3(NBK, 2), 256>>>(hmean,
            Wq + (size_t)L * DIMM * DIMM, Wkv + (size_t)L * DIMM * 2 * DIMM);
        routing_kernel<<<BHN, NB>>>();
        attn_kernel<<<dim3(NB, BHN), 256>>>(qkv, o);
        hmma_gemm<<<dim3(2, MROWS / 128), 256, GEMM_SMEM>>>(o, DIMM, woh + oo, wol + oo, DIMM,
            bo_, y, y, nullptr, DIMM, DIMM, 0);
        ln_h_kernel<<<MROWS / 8, 256>>>(y, h, ln2_g + (size_t)L * DIMM, ln2_b + (size_t)L * DIMM);
        hmma_gemm<<<dim3(8, MROWS / 128), 256, GEMM_SMEM>>>(h, DIMM, w1h + off1, w1l + off1, DIMM,
            bb1, nullptr, nullptr, ff, FFD, DIMM, 1);
        hmma_gemm<<<dim3(2, MROWS / 128), 256, GEMM_SMEM>>>(ff, FFD, w2h + off1, w2l + off1, FFD,
            bb2, y, y, nullptr, DIMM, FFD, 0);
    }

    ln_kernel<<<MROWS / 8, 256>>>(y, qkv, gf, bf);   // reuse qkv as scratch
    out_transpose_kernel<<<tg, tb>>>(qkv, out);
    (void)in_sizes; (void)n_in; (void)out_size;
}

// round 6
// speedup vs baseline: 3.3612x; 1.1666x over previous
#include <cuda_runtime.h>
#include <cuda_fp16.h>
#include <math.h>
#include <cstdint>

#define DIMM   256
#define TT     8192
#define BB     4
#define HEADSN 8
#define DH     32
#define NB     128
#define BUCKET 64
#define FFD    1024
#define DEPTHN 6
#define MROWS  (BB*TT)
#define BHN    (BB*HEADSN)
#define QKVD   768
#define NBK    (BB*NB)

// ======================= static device scratch =======================
__device__ float g_y  [MROWS*DIMM];
__device__ __half g_qkv[MROWS*QKVD];
__device__ __half g_h [MROWS*DIMM];
__device__ __half g_o [MROWS*DIMM];
__device__ __half g_ff[MROWS*FFD];
__device__ __half g_wqkv[DEPTHN*QKVD*DIMM];
__device__ __half g_wo  [DEPTHN*DIMM*DIMM];
__device__ __half g_w1  [DEPTHN*DIMM*FFD];
__device__ __half g_w2  [DEPTHN*FFD*DIMM];
__device__ float g_hmean[NBK*DIMM];
__device__ float g_sq[BHN*NB*DH];
__device__ float g_sk[BHN*NB*DH];
__device__ float g_top[BHN*NB];
__device__ int   g_idx[BHN*NB];

// ======================= helpers =======================
__device__ __forceinline__ uint32_t smem_u32(const void* p) {
    uint32_t a;
    asm("{ .reg .u64 t; cvta.to.shared.u64 t, %1; cvt.u32.u64 %0, t; }" : "=r"(a) : "l"(p));
    return a;
}

#define MMA_F16(c, a, b) \
    asm volatile("mma.sync.aligned.m16n8k16.row.col.f32.f16.f16.f32 " \
        "{%0,%1,%2,%3}, {%4,%5,%6,%7}, {%8,%9}, {%0,%1,%2,%3};" \
        : "+f"((c)[0]), "+f"((c)[1]), "+f"((c)[2]), "+f"((c)[3]) \
        : "r"((a)[0]), "r"((a)[1]), "r"((a)[2]), "r"((a)[3]), "r"((b)[0]), "r"((b)[1]))

#define LDSM_X4(r, addr) \
    asm volatile("ldmatrix.sync.aligned.m8n8.x4.shared.b16 {%0,%1,%2,%3}, [%4];" \
        : "=r"((r)[0]), "=r"((r)[1]), "=r"((r)[2]), "=r"((r)[3]) : "r"(addr))

#define CP_ASYNC16(dst, src) \
    asm volatile("cp.async.cg.shared.global [%0], [%1], 16;" :: "r"(dst), "l"(src))
#define CP_COMMIT()  asm volatile("cp.async.commit_group;" ::: "memory")
#define CP_WAIT(n)   asm volatile("cp.async.wait_group %0;" :: "n"(n) : "memory")

// ======================= small kernels =======================
__global__ void pos_add_kernel(const float* __restrict__ x, const float* __restrict__ pe0,
                               const float* __restrict__ pe1, float* __restrict__ y) {
    __shared__ float tile[32][33];
    int b = blockIdx.z, d0 = blockIdx.y * 32, t0 = blockIdx.x * 32;
    int tx = threadIdx.x, ty = threadIdx.y;
    const float* xb = x + (size_t)b * DIMM * TT;
    #pragma unroll
    for (int i = 0; i < 32; i += 8)
        tile[ty + i][tx] = xb[(size_t)(d0 + ty + i) * TT + t0 + tx];
    __syncthreads();
    float* yb = y + (size_t)b * TT * DIMM;
    #pragma unroll
    for (int i = 0; i < 32; i += 8) {
        int t = t0 + ty + i, d = d0 + tx;
        yb[(size_t)t * DIMM + d] =
            tile[tx][ty + i] + pe0[(size_t)(t >> 6) * DIMM + d] + pe1[(size_t)(t & 63) * DIMM + d];
    }
}

__global__ void out_transpose_kernel(const float* __restrict__ hin, float* __restrict__ out) {
    __shared__ float tile[32][33];
    int b = blockIdx.z, d0 = blockIdx.y * 32, t0 = blockIdx.x * 32;
    int tx = threadIdx.x, ty = threadIdx.y;
    const float* hb = hin + (size_t)b * TT * DIMM;
    #pragma unroll
    for (int i = 0; i < 32; i += 8)
        tile[ty + i][tx] = hb[(size_t)(t0 + ty + i) * DIMM + d0 + tx];
    __syncthreads();
    float* ob = out + (size_t)b * DIMM * TT;
    #pragma unroll
    for (int i = 0; i < 32; i += 8)
        ob[(size_t)(d0 + ty + i) * TT + t0 + tx] = tile[tx][ty + i];
}

// LN -> fp32 (final)
__global__ void ln_kernel(const float* __restrict__ in, float* __restrict__ out,
                          const float* __restrict__ g, const float* __restrict__ b) {
    int row = blockIdx.x * 8 + (threadIdx.x >> 5);
    int lane = threadIdx.x & 31;
    const float* r = in + (size_t)row * DIMM;
    float v[8], s = 0.f;
    #pragma unroll
    for (int i = 0; i < 8; i++) { v[i] = r[lane + i * 32]; s += v[i]; }
    #pragma unroll
    for (int off = 16; off; off >>= 1) s += __shfl_xor_sync(0xffffffffu, s, off);
    float m = s * (1.0f / DIMM), var = 0.f;
    #pragma unroll
    for (int i = 0; i < 8; i++) { float d = v[i] - m; var += d * d; }
    #pragma unroll
    for (int off = 16; off; off >>= 1) var += __shfl_xor_sync(0xffffffffu, var, off);
    float inv = rsqrtf(var * (1.0f / DIMM) + 1e-5f);
    float* o = out + (size_t)row * DIMM;
    #pragma unroll
    for (int i = 0; i < 8; i++) {
        int c = lane + i * 32;
        o[c] = (v[i] - m) * inv * g[c] + b[c];
    }
}

// LN -> fp16 only (used for LN2)
__global__ void ln_h_kernel(const float* __restrict__ in, __half* __restrict__ oh,
                            const float* __restrict__ g, const float* __restrict__ b) {
    int row = blockIdx.x * 8 + (threadIdx.x >> 5);
    int lane = threadIdx.x & 31;
    const float* r = in + (size_t)row * DIMM;
    float v[8], s = 0.f;
    #pragma unroll
    for (int i = 0; i < 8; i++) { v[i] = r[lane + i * 32]; s += v[i]; }
    #pragma unroll
    for (int off = 16; off; off >>= 1) s += __shfl_xor_sync(0xffffffffu, s, off);
    float m = s * (1.0f / DIMM), var = 0.f;
    #pragma unroll
    for (int i = 0; i < 8; i++) { float d = v[i] - m; var += d * d; }
    #pragma unroll
    for (int off = 16; off; off >>= 1) var += __shfl_xor_sync(0xffffffffu, var, off);
    float inv = rsqrtf(var * (1.0f / DIMM) + 1e-5f);
    #pragma unroll
    for (int i = 0; i < 8; i++) {
        int c = lane + i * 32;
        oh[(size_t)row * DIMM + c] = __float2half((v[i] - m) * inv * g[c] + b[c]);
    }
}

// LN1 fused: per-row LN -> fp16 h AND exact fp32 bucket means (1 block = 1 bucket = 64 rows)
__global__ void ln1_fused_kernel(const float* __restrict__ y, __half* __restrict__ oh,
                                 const float* __restrict__ g, const float* __restrict__ b,
                                 float* __restrict__ hmean) {
    __shared__ float acc[8][DIMM];
    int bu = blockIdx.x;
    int warp = threadIdx.x >> 5, lane = threadIdx.x & 31;
    float la[8];
    #pragma unroll
    for (int i = 0; i < 8; i++) la[i] = 0.f;
    for (int rr = 0; rr < 8; rr++) {
        int row = bu * BUCKET + warp * 8 + rr;
        const float* r = y + (size_t)row * DIMM;
        float v[8], s = 0.f;
        #pragma unroll
        for (int i = 0; i < 8; i++) { v[i] = r[lane + i * 32]; s += v[i]; }
        #pragma unroll
        for (int off = 16; off; off >>= 1) s += __shfl_xor_sync(0xffffffffu, s, off);
        float m = s * (1.0f / DIMM), var = 0.f;
        #pragma unroll
        for (int i = 0; i < 8; i++) { float d = v[i] - m; var += d * d; }
        #pragma unroll
        for (int off = 16; off; off >>= 1) var += __shfl_xor_sync(0xffffffffu, var, off);
        float inv = rsqrtf(var * (1.0f / DIMM) + 1e-5f);
        #pragma unroll
        for (int i = 0; i < 8; i++) {
            int c = lane + i * 32;
            float val = (v[i] - m) * inv * g[c] + b[c];
            oh[(size_t)row * DIMM + c] = __float2half(val);
            la[i] += val;
        }
    }
    #pragma unroll
    for (int i = 0; i < 8; i++) acc[warp][lane + i * 32] = la[i];
    __syncthreads();
    for (int c = threadIdx.x; c < DIMM; c += 256) {
        float s = 0.f;
        #pragma unroll
        for (int w = 0; w < 8; w++) s += acc[w][c];
        hmean[(size_t)bu * DIMM + c] = s * (1.0f / BUCKET);
    }
}

// small fp32 gemm: sq/sk = hmean @ Wq / Wkv[:, :256]  (exact routing)
__global__ void route_gemm_kernel(const float* __restrict__ hmean,
                                  const float* __restrict__ Wq, const float* __restrict__ Wkv) {
    __shared__ float hm[DIMM];
    int row = blockIdx.x;
    int sel = blockIdx.y;
    int c = threadIdx.x;
    hm[c] = hmean[(size_t)row * DIMM + c];
    __syncthreads();
    const float* W = sel ? Wkv : Wq;
    int ldw = sel ? 2 * DIMM : DIMM;
    float a = 0.f;
    #pragma unroll 8
    for (int k = 0; k < DIMM; k++) a = fmaf(hm[k], W[(size_t)k * ldw + c], a);
    int b = row >> 7, u = row & 127;
    int h = c >> 5, e = c & 31;
    size_t dst = (((size_t)(b * HEADSN + h)) * NB + u) * DH + e;
    if (sel) g_sk[dst] = a; else g_sq[dst] = a;
}

// W (K,N) fp32 -> WT (N,K) fp16
__global__ void wconv_kernel(const float* __restrict__ W, __half* __restrict__ T,
                             int K, int N, size_t lstride) {
    __shared__ float t[32][33];
    int l = blockIdx.z;
    const float* Wl = W + (size_t)l * K * N;
    size_t ob = (size_t)l * lstride;
    int n0 = blockIdx.x * 32, k0 = blockIdx.y * 32;
    int tx = threadIdx.x, ty = threadIdx.y;
    #pragma unroll
    for (int i = 0; i < 32; i += 8)
        t[ty + i][tx] = Wl[(size_t)(k0 + ty + i) * N + n0 + tx];
    __syncthreads();
    #pragma unroll
    for (int i = 0; i < 32; i += 8)
        T[ob + (size_t)(n0 + ty + i) * K + k0 + tx] = __float2half(t[tx][ty + i]);
}

// ======================= pipelined fp16 HMMA GEMM (1-term) =======================
// C = A(M,K) @ B^T(N,K). CTA 128x128, K-chunk 64, 3-stage cp.async.
#define AH_OFF 0
#define BH_OFF 16384
#define STAGE_SZ 32768
#define NSTAGE 3
#define GEMM_SMEM (NSTAGE*STAGE_SZ)

__device__ __forceinline__ void gemm_load_stage(
    uint32_t sb, int stg, int tid, int k0,
    const __half* __restrict__ Ah, int lda,
    const __half* __restrict__ Bh, int ldb,
    int m0, int n0) {
    uint32_t base = sb + stg * STAGE_SZ;
    #pragma unroll
    for (int p = 0; p < 4; ++p) {
        int lin = p * 256 + tid;
        int r = lin >> 3, kb = lin & 7;
        uint32_t soff = (uint32_t)(r * 128 + ((kb ^ (r & 7)) << 4));
        CP_ASYNC16(base + AH_OFF + soff, Ah + (size_t)(m0 + r) * lda + k0 + kb * 8);
        CP_ASYNC16(base + BH_OFF + soff, Bh + (size_t)(n0 + r) * ldb + k0 + kb * 8);
    }
}

__global__ __launch_bounds__(256)
void hmma_gemm(const __half* __restrict__ Ah, int lda,
               const __half* __restrict__ Bh, int ldb,
               const float* __restrict__ bias, const float* __restrict__ resid,
               float* __restrict__ Cf, __half* __restrict__ Ch,
               int ldc, int K, int gelu) {
    extern __shared__ char smem[];
    uint32_t sb = smem_u32(smem);
    int tid = threadIdx.x;
    int lane = tid & 31, wid = tid >> 5;
    int wm = wid >> 2, wn = wid & 3;
    int m0 = blockIdx.y * 128, n0 = blockIdx.x * 128;

    float acc[4][4][4];
    #pragma unroll
    for (int i = 0; i < 4; i++)
        #pragma unroll
        for (int j = 0; j < 4; j++)
            #pragma unroll
            for (int k = 0; k < 4; k++) acc[i][j][k] = 0.f;

    int a_row = (lane & 15);
    int a_kh  = (lane >> 4);
    int b_sub = (lane >> 3);
    int b_row = ((b_sub >> 1) << 3) + (lane & 7);
    int b_kh  = (b_sub & 1);

    const int nch = K >> 6;
    gemm_load_stage(sb, 0, tid, 0, Ah, lda, Bh, ldb, m0, n0);
    CP_COMMIT();
    if (nch > 1) {
        gemm_load_stage(sb, 1, tid, 64, Ah, lda, Bh, ldb, m0, n0);
        CP_COMMIT();
    }

    for (int ch = 0; ch < nch; ++ch) {
        if (ch + 2 < nch) {
            gemm_load_stage(sb, (ch + 2) % NSTAGE, tid, (ch + 2) << 6, Ah, lda, Bh, ldb, m0, n0);
            CP_COMMIT();
            CP_WAIT(2);
        } else if (ch + 1 < nch) {
            CP_WAIT(1);
        } else {
            CP_WAIT(0);
        }
        __syncthreads();

        uint32_t stg = sb + (ch % NSTAGE) * STAGE_SZ;
        #pragma unroll
        for (int ks = 0; ks < 4; ++ks) {
            uint32_t bh[4][2];
            #pragma unroll
            for (int pair = 0; pair < 2; ++pair) {
                int row = wn * 32 + pair * 16 + b_row;
                int kb = ks * 2 + b_kh;
                uint32_t addr = stg + (uint32_t)(row * 128 + ((kb ^ (row & 7)) << 4));
                uint32_t rg[4];
                LDSM_X4(rg, addr + BH_OFF);
                bh[pair * 2][0] = rg[0]; bh[pair * 2][1] = rg[1];
                bh[pair * 2 + 1][0] = rg[2]; bh[pair * 2 + 1][1] = rg[3];
            }
            #pragma unroll
            for (int mt = 0; mt < 4; ++mt) {
                int row = wm * 64 + mt * 16 + a_row;
                int kb = ks * 2 + a_kh;
                uint32_t addr = stg + (uint32_t)(row * 128 + ((kb ^ (row & 7)) << 4));
                uint32_t ah[4];
                LDSM_X4(ah, addr + AH_OFF);
                #pragma unroll
                for (int nt = 0; nt < 4; ++nt)
                    MMA_F16(acc[mt][nt], ah, bh[nt]);
            }
        }
        __syncthreads();
    }

    int rbase = m0 + wm * 64 + (lane >> 2);
    int cbase = n0 + wn * 32 + (lane & 3) * 2;
    #pragma unroll
    for (int mt = 0; mt < 4; ++mt) {
        #pragma unroll
        for (int nt = 0; nt < 4; ++nt) {
            #pragma unroll
            for (int half = 0; half < 2; ++half) {
                int gm = rbase + mt * 16 + half * 8;
                int gn = cbase + nt * 8;
                float v0 = acc[mt][nt][half * 2 + 0];
                float v1 = acc[mt][nt][half * 2 + 1];
                if (bias) { v0 += bias[gn]; v1 += bias[gn + 1]; }
                if (gelu) {
                    v0 = 0.5f * v0 * (1.0f + erff(v0 * 0.70710678118654752f));
                    v1 = 0.5f * v1 * (1.0f + erff(v1 * 0.70710678118654752f));
                }
                size_t go = (size_t)gm * ldc + gn;
                if (resid) { v0 += resid[go]; v1 += resid[go + 1]; }
                if (Cf) {
                    *reinterpret_cast<float2*>(Cf + go) = make_float2(v0, v1);
                } else {
                    *reinterpret_cast<__half2*>(Ch + go) = __floats2half2_rn(v0, v1);
                }
            }
        }
    }
}

// ======================= attention =======================
__global__ void routing_kernel() {
    int bh = blockIdx.x;
    int i = threadIdx.x;
    __shared__ float ssk[NB][DH];
    const float* base = g_sk + (size_t)bh * NB * DH;
    for (int idx = i; idx < NB * DH; idx += NB) ssk[idx / DH][idx % DH] = base[idx];
    float sq[DH];
    const float* sqp = g_sq + ((size_t)bh * NB + i) * DH;
    #pragma unroll
    for (int e = 0; e < DH; e++) sq[e] = sqp[e];
    __syncthreads();
    const float sc = 0.17677669529663687f * (1.0f / 0.75f);
    float mx = -1e30f; int am = 0;
    for (int j = 0; j < NB; j++) {
        float d = 0.f;
        #pragma unroll
        for (int e = 0; e < DH; e++) d = fmaf(sq[e], ssk[j][e], d);
        d *= sc;
        if (d > mx) { mx = d; am = j; }
    }
    float sum = 0.f;
    for (int j = 0; j < NB; j++) {
        float d = 0.f;
        #pragma unroll
        for (int e = 0; e < DH; e++) d = fmaf(sq[e], ssk[j][e], d);
        sum += expf(d * sc - mx);
    }
    g_top[bh * NB + i] = 1.0f / sum;
    g_idx[bh * NB + i] = am;
}

__global__ void attn_kernel(const __half* __restrict__ qkv, __half* __restrict__ o) {
    int u = blockIdx.x, bh = blockIdx.y;
    int b = bh >> 3, h = bh & 7;
    __shared__ float sQ[64][DH];
    __shared__ float sK[128][DH + 1];
    __shared__ float sV[128][DH];
    __shared__ float sP[8][128];
    int tid = threadIdx.x;
    int warp = tid >> 5, lane = tid & 31;
    float top = g_top[bh * NB + u];
    int ridx = g_idx[bh * NB + u];
    const __half* qbase = qkv + ((size_t)(b * TT + u * BUCKET)) * QKVD + h * DH;
    const __half* kself = qbase + 256;
    const __half* krout = qkv + ((size_t)(b * TT + ridx * BUCKET)) * QKVD + 256 + h * DH;
    for (int i = tid; i < 64 * DH; i += 256) {
        int r = i >> 5, e = i & 31;
        sQ[r][e]      = __half2float(qbase[(size_t)r * QKVD + e]);
        sK[r][e]      = top * __half2float(krout[(size_t)r * QKVD + e]);
        sV[r][e]      = top * __half2float(krout[(size_t)r * QKVD + 256 + e]);
        sK[64 + r][e] =       __half2float(kself[(size_t)r * QKVD + e]);
        sV[64 + r][e] =       __half2float(kself[(size_t)r * QKVD + 256 + e]);
    }
    __syncthreads();
    const float scale = 0.17677669529663687f;
    size_t obase = ((size_t)(b * TT + u * BUCKET)) * DIMM + h * DH;
    for (int rr = 0; rr < 8; rr++) {
        int r = warp * 8 + rr;
        float d[4];
        #pragma unroll
        for (int c = 0; c < 4; c++) {
            int j = lane + c * 32;
            float a = 0.f;
            #pragma unroll
            for (int e = 0; e < DH; e++) a = fmaf(sQ[r][e], sK[j][e], a);
            d[c] = a * scale;
        }
        float mx = fmaxf(fmaxf(d[0], d[1]), fmaxf(d[2], d[3]));
        #pragma unroll
        for (int off = 16; off; off >>= 1) mx = fmaxf(mx, __shfl_xor_sync(0xffffffffu, mx, off));
        float p[4], s = 0.f;
        #pragma unroll
        for (int c = 0; c < 4; c++) { p[c] = __expf(d[c] - mx); s += p[c]; }
        #pragma unroll
        for (int off = 16; off; off >>= 1) s += __shfl_xor_sync(0xffffffffu, s, off);
        float inv = 1.0f / s;
        #pragma unroll
        for (int c = 0; c < 4; c++) sP[warp][lane + c * 32] = p[c] * inv;
        __syncwarp();
        float a = 0.f;
        #pragma unroll
        for (int j = 0; j < 128; j++) a = fmaf(sP[warp][j], sV[j][lane], a);
        o[obase + (size_t)r * DIMM + lane] = __float2half(a);
        __syncwarp();
    }
}

// ======================= host orchestration =======================
extern "C" void kernel_launch(void* const* d_in, const int* in_sizes, int n_in,
                              void* d_out, int out_size) {
    const float* x     = (const float*)d_in[0];
    const float* pe0   = (const float*)d_in[1];
    const float* pe1   = (const float*)d_in[2];
    const float* ln1_g = (const float*)d_in[3];
    const float* ln1_b = (const float*)d_in[4];
    const float* Wq    = (const float*)d_in[5];
    const float* Wkv   = (const float*)d_in[6];
    const float* Wo    = (const float*)d_in[7];
    const float* bo    = (const float*)d_in[8];
    const float* ln2_g = (const float*)d_in[9];
    const float* ln2_b = (const float*)d_in[10];
    const float* W1    = (const float*)d_in[11];
    const float* b1    = (const float*)d_in[12];
    const float* W2    = (const float*)d_in[13];
    const float* b2    = (const float*)d_in[14];
    const float* gf    = (const float*)d_in[15];
    const float* bf    = (const float*)d_in[16];
    float* out = (float*)d_out;

    cudaFuncSetAttribute(hmma_gemm, cudaFuncAttributeMaxDynamicSharedMemorySize, GEMM_SMEM);

    float *y, *hmean;
    __half *qkv, *h, *o, *ff;
    __half *wqkv, *wo, *w1, *w2;
    cudaGetSymbolAddress((void**)&y, g_y);
    cudaGetSymbolAddress((void**)&qkv, g_qkv);
    cudaGetSymbolAddress((void**)&hmean, g_hmean);
    cudaGetSymbolAddress((void**)&h, g_h);
    cudaGetSymbolAddress((void**)&o, g_o);
    cudaGetSymbolAddress((void**)&ff, g_ff);
    cudaGetSymbolAddress((void**)&wqkv, g_wqkv);
    cudaGetSymbolAddress((void**)&wo, g_wo);
    cudaGetSymbolAddress((void**)&w1, g_w1);
    cudaGetSymbolAddress((void**)&w2, g_w2);

    dim3 tb(32, 8);
    const size_t QKV_LS = (size_t)QKVD * DIMM;
    wconv_kernel<<<dim3(DIMM / 32,   DIMM / 32, DEPTHN), tb>>>(Wq,  wqkv, DIMM, DIMM, QKV_LS);
    wconv_kernel<<<dim3(2*DIMM / 32, DIMM / 32, DEPTHN), tb>>>(Wkv, wqkv + 256 * DIMM, DIMM, 2*DIMM, QKV_LS);
    wconv_kernel<<<dim3(DIMM / 32,   DIMM / 32, DEPTHN), tb>>>(Wo,  wo, DIMM, DIMM, (size_t)DIMM * DIMM);
    wconv_kernel<<<dim3(FFD / 32,    DIMM / 32, DEPTHN), tb>>>(W1,  w1, DIMM, FFD, (size_t)DIMM * FFD);
    wconv_kernel<<<dim3(DIMM / 32,   FFD / 32,  DEPTHN), tb>>>(W2,  w2, FFD,  DIMM, (size_t)DIMM * FFD);

    dim3 tg(TT / 32, DIMM / 32, BB);
    pos_add_kernel<<<tg, tb>>>(x, pe0, pe1, y);

    for (int L = 0; L < DEPTHN; L++) {
        const float* g1 = ln1_g + (size_t)L * DIMM;
        const float* bb = ln1_b + (size_t)L * DIMM;
        const float* bo_ = bo + (size_t)L * DIMM;
        const float* bb1 = b1 + (size_t)L * FFD;
        const float* bb2 = b2 + (size_t)L * DIMM;
        size_t oqkv = (size_t)L * QKV_LS;
        size_t oo   = (size_t)L * DIMM * DIMM;
        size_t off1 = (size_t)L * DIMM * FFD;

        ln1_fused_kernel<<<NBK, 256>>>(y, h, g1, bb, hmean);
        route_gemm_kernel<<<dim3(NBK, 2), 256>>>(hmean,
            Wq + (size_t)L * DIMM * DIMM, Wkv + (size_t)L * DIMM * 2 * DIMM);
        routing_kernel<<<BHN, NB>>>();
        hmma_gemm<<<dim3(QKVD / 128, MROWS / 128), 256, GEMM_SMEM>>>(h, DIMM,
            wqkv + oqkv, DIMM, nullptr, nullptr, nullptr, qkv, QKVD, DIMM, 0);
        attn_kernel<<<dim3(NB, BHN), 256>>>(qkv, o);
        hmma_gemm<<<dim3(2, MROWS / 128), 256, GEMM_SMEM>>>(o, DIMM, wo + oo, DIMM,
            bo_, y, y, nullptr, DIMM, DIMM, 0);
        ln_h_kernel<<<MROWS / 8, 256>>>(y, h, ln2_g + (size_t)L * DIMM, ln2_b + (size_t)L * DIMM);
        hmma_gemm<<<dim3(8, MROWS / 128), 256, GEMM_SMEM>>>(h, DIMM, w1 + off1, DIMM,
            bb1, nullptr, nullptr, ff, FFD, DIMM, 1);
        hmma_gemm<<<dim3(2, MROWS / 128), 256, GEMM_SMEM>>>(ff, FFD, w2 + off1, FFD,
            bb2, y, y, nullptr, DIMM, FFD, 0);
    }

    ln_kernel<<<MROWS / 8, 256>>>(y, (float*)qkv, gf, bf);   // reuse qkv as fp32 scratch
    out_transpose_kernel<<<tg, tb>>>((float*)qkv, out);
    (void)in_sizes; (void)n_in; (void)out_size;
}

// round 8
// speedup vs baseline: 5.9397x; 1.7671x over previous
#include <cuda_runtime.h>
#include <cuda_fp16.h>
#include <math.h>
#include <cstdint>

#define DIMM   256
#define TT     8192
#define BB     4
#define HEADSN 8
#define DH     32
#define NB     128
#define BUCKET 64
#define FFD    1024
#define DEPTHN 6
#define MROWS  (BB*TT)
#define BHN    (BB*HEADSN)
#define QKVD   768
#define NBK    (BB*NB)

// ======================= static device scratch =======================
__device__ float g_y  [MROWS*DIMM];
__device__ __half g_qkv[MROWS*QKVD];
__device__ __half g_h [MROWS*DIMM];
__device__ __half g_o [MROWS*DIMM];
__device__ __half g_ff[MROWS*FFD];
__device__ __half g_wqkv[DEPTHN*QKVD*DIMM];
__device__ __half g_wo  [DEPTHN*DIMM*DIMM];
__device__ __half g_w1  [DEPTHN*DIMM*FFD];
__device__ __half g_w2  [DEPTHN*FFD*DIMM];
__device__ float g_hmean[NBK*DIMM];
__device__ float g_sq[BHN*NB*DH];
__device__ float g_sk[BHN*NB*DH];
__device__ float g_top[BHN*NB];
__device__ int   g_idx[BHN*NB];

// ======================= helpers =======================
__device__ __forceinline__ uint32_t smem_u32(const void* p) {
    uint32_t a;
    asm("{ .reg .u64 t; cvta.to.shared.u64 t, %1; cvt.u32.u64 %0, t; }" : "=r"(a) : "l"(p));
    return a;
}
__device__ __forceinline__ uint32_t pack_half2(float a, float b) {
    __half2 h = __floats2half2_rn(a, b);
    return *reinterpret_cast<uint32_t*>(&h);
}

#define MMA_F16(c, a, b0, b1) \
    asm volatile("mma.sync.aligned.m16n8k16.row.col.f32.f16.f16.f32 " \
        "{%0,%1,%2,%3}, {%4,%5,%6,%7}, {%8,%9}, {%0,%1,%2,%3};" \
        : "+f"((c)[0]), "+f"((c)[1]), "+f"((c)[2]), "+f"((c)[3]) \
        : "r"((a)[0]), "r"((a)[1]), "r"((a)[2]), "r"((a)[3]), "r"(b0), "r"(b1))

#define LDSM_X4(r, addr) \
    asm volatile("ldmatrix.sync.aligned.m8n8.x4.shared.b16 {%0,%1,%2,%3}, [%4];" \
        : "=r"((r)[0]), "=r"((r)[1]), "=r"((r)[2]), "=r"((r)[3]) : "r"(addr))

#define LDSM_X4_T(r, addr) \
    asm volatile("ldmatrix.sync.aligned.m8n8.x4.trans.shared.b16 {%0,%1,%2,%3}, [%4];" \
        : "=r"((r)[0]), "=r"((r)[1]), "=r"((r)[2]), "=r"((r)[3]) : "r"(addr))

#define CP_ASYNC16(dst, src) \
    asm volatile("cp.async.cg.shared.global [%0], [%1], 16;" :: "r"(dst), "l"(src))
#define CP_COMMIT()  asm volatile("cp.async.commit_group;" ::: "memory")
#define CP_WAIT(n)   asm volatile("cp.async.wait_group %0;" :: "n"(n) : "memory")

// ======================= small kernels =======================
__global__ void pos_add_kernel(const float* __restrict__ x, const float* __restrict__ pe0,
                               const float* __restrict__ pe1, float* __restrict__ y) {
    __shared__ float tile[32][33];
    int b = blockIdx.z, d0 = blockIdx.y * 32, t0 = blockIdx.x * 32;
    int tx = threadIdx.x, ty = threadIdx.y;
    const float* xb = x + (size_t)b * DIMM * TT;
    #pragma unroll
    for (int i = 0; i < 32; i += 8)
        tile[ty + i][tx] = xb[(size_t)(d0 + ty + i) * TT + t0 + tx];
    __syncthreads();
    float* yb = y + (size_t)b * TT * DIMM;
    #pragma unroll
    for (int i = 0; i < 32; i += 8) {
        int t = t0 + ty + i, d = d0 + tx;
        yb[(size_t)t * DIMM + d] =
            tile[tx][ty + i] + pe0[(size_t)(t >> 6) * DIMM + d] + pe1[(size_t)(t & 63) * DIMM + d];
    }
}

__global__ void out_transpose_kernel(const float* __restrict__ hin, float* __restrict__ out) {
    __shared__ float tile[32][33];
    int b = blockIdx.z, d0 = blockIdx.y * 32, t0 = blockIdx.x * 32;
    int tx = threadIdx.x, ty = threadIdx.y;
    const float* hb = hin + (size_t)b * TT * DIMM;
    #pragma unroll
    for (int i = 0; i < 32; i += 8)
        tile[ty + i][tx] = hb[(size_t)(t0 + ty + i) * DIMM + d0 + tx];
    __syncthreads();
    float* ob = out + (size_t)b * DIMM * TT;
    #pragma unroll
    for (int i = 0; i < 32; i += 8)
        ob[(size_t)(d0 + ty + i) * TT + t0 + tx] = tile[tx][ty + i];
}

__global__ void ln_kernel(const float* __restrict__ in, float* __restrict__ out,
                          const float* __restrict__ g, const float* __restrict__ b) {
    int row = blockIdx.x * 8 + (threadIdx.x >> 5);
    int lane = threadIdx.x & 31;
    const float* r = in + (size_t)row * DIMM;
    float v[8], s = 0.f;
    #pragma unroll
    for (int i = 0; i < 8; i++) { v[i] = r[lane + i * 32]; s += v[i]; }
    #pragma unroll
    for (int off = 16; off; off >>= 1) s += __shfl_xor_sync(0xffffffffu, s, off);
    float m = s * (1.0f / DIMM), var = 0.f;
    #pragma unroll
    for (int i = 0; i < 8; i++) { float d = v[i] - m; var += d * d; }
    #pragma unroll
    for (int off = 16; off; off >>= 1) var += __shfl_xor_sync(0xffffffffu, var, off);
    float inv = rsqrtf(var * (1.0f / DIMM) + 1e-5f);
    float* o = out + (size_t)row * DIMM;
    #pragma unroll
    for (int i = 0; i < 8; i++) {
        int c = lane + i * 32;
        o[c] = (v[i] - m) * inv * g[c] + b[c];
    }
}

__global__ void ln_h_kernel(const float* __restrict__ in, __half* __restrict__ oh,
                            const float* __restrict__ g, const float* __restrict__ b) {
    int row = blockIdx.x * 8 + (threadIdx.x >> 5);
    int lane = threadIdx.x & 31;
    const float* r = in + (size_t)row * DIMM;
    float v[8], s = 0.f;
    #pragma unroll
    for (int i = 0; i < 8; i++) { v[i] = r[lane + i * 32]; s += v[i]; }
    #pragma unroll
    for (int off = 16; off; off >>= 1) s += __shfl_xor_sync(0xffffffffu, s, off);
    float m = s * (1.0f / DIMM), var = 0.f;
    #pragma unroll
    for (int i = 0; i < 8; i++) { float d = v[i] - m; var += d * d; }
    #pragma unroll
    for (int off = 16; off; off >>= 1) var += __shfl_xor_sync(0xffffffffu, var, off);
    float inv = rsqrtf(var * (1.0f / DIMM) + 1e-5f);
    #pragma unroll
    for (int i = 0; i < 8; i++) {
        int c = lane + i * 32;
        oh[(size_t)row * DIMM + c] = __float2half((v[i] - m) * inv * g[c] + b[c]);
    }
}

__global__ void ln1_fused_kernel(const float* __restrict__ y, __half* __restrict__ oh,
                                 const float* __restrict__ g, const float* __restrict__ b,
                                 float* __restrict__ hmean) {
    __shared__ float acc[8][DIMM];
    int bu = blockIdx.x;
    int warp = threadIdx.x >> 5, lane = threadIdx.x & 31;
    float la[8];
    #pragma unroll
    for (int i = 0; i < 8; i++) la[i] = 0.f;
    for (int rr = 0; rr < 8; rr++) {
        int row = bu * BUCKET + warp * 8 + rr;
        const float* r = y + (size_t)row * DIMM;
        float v[8], s = 0.f;
        #pragma unroll
        for (int i = 0; i < 8; i++) { v[i] = r[lane + i * 32]; s += v[i]; }
        #pragma unroll
        for (int off = 16; off; off >>= 1) s += __shfl_xor_sync(0xffffffffu, s, off);
        float m = s * (1.0f / DIMM), var = 0.f;
        #pragma unroll
        for (int i = 0; i < 8; i++) { float d = v[i] - m; var += d * d; }
        #pragma unroll
        for (int off = 16; off; off >>= 1) var += __shfl_xor_sync(0xffffffffu, var, off);
        float inv = rsqrtf(var * (1.0f / DIMM) + 1e-5f);
        #pragma unroll
        for (int i = 0; i < 8; i++) {
            int c = lane + i * 32;
            float val = (v[i] - m) * inv * g[c] + b[c];
            oh[(size_t)row * DIMM + c] = __float2half(val);
            la[i] += val;
        }
    }
    #pragma unroll
    for (int i = 0; i < 8; i++) acc[warp][lane + i * 32] = la[i];
    __syncthreads();
    for (int c = threadIdx.x; c < DIMM; c += 256) {
        float s = 0.f;
        #pragma unroll
        for (int w = 0; w < 8; w++) s += acc[w][c];
        hmean[(size_t)bu * DIMM + c] = s * (1.0f / BUCKET);
    }
}

__global__ void route_gemm_kernel(const float* __restrict__ hmean,
                                  const float* __restrict__ Wq, const float* __restrict__ Wkv) {
    __shared__ float hm[DIMM];
    int row = blockIdx.x;
    int sel = blockIdx.y;
    int c = threadIdx.x;
    hm[c] = hmean[(size_t)row * DIMM + c];
    __syncthreads();
    const float* W = sel ? Wkv : Wq;
    int ldw = sel ? 2 * DIMM : DIMM;
    float a = 0.f;
    #pragma unroll 8
    for (int k = 0; k < DIMM; k++) a = fmaf(hm[k], W[(size_t)k * ldw + c], a);
    int b = row >> 7, u = row & 127;
    int h = c >> 5, e = c & 31;
    size_t dst = (((size_t)(b * HEADSN + h)) * NB + u) * DH + e;
    if (sel) g_sk[dst] = a; else g_sq[dst] = a;
}

__global__ void wconv_kernel(const float* __restrict__ W, __half* __restrict__ T,
                             int K, int N, size_t lstride) {
    __shared__ float t[32][33];
    int l = blockIdx.z;
    const float* Wl = W + (size_t)l * K * N;
    size_t ob = (size_t)l * lstride;
    int n0 = blockIdx.x * 32, k0 = blockIdx.y * 32;
    int tx = threadIdx.x, ty = threadIdx.y;
    #pragma unroll
    for (int i = 0; i < 32; i += 8)
        t[ty + i][tx] = Wl[(size_t)(k0 + ty + i) * N + n0 + tx];
    __syncthreads();
    #pragma unroll
    for (int i = 0; i < 32; i += 8)
        T[ob + (size_t)(n0 + ty + i) * K + k0 + tx] = __float2half(t[tx][ty + i]);
}

// ======================= pipelined fp16 HMMA GEMM =======================
#define AH_OFF 0
#define BH_OFF 16384
#define STAGE_SZ 32768
#define NSTAGE 3
#define GEMM_SMEM (NSTAGE*STAGE_SZ)

__device__ __forceinline__ void gemm_load_stage(
    uint32_t sb, int stg, int tid, int k0,
    const __half* __restrict__ Ah, int lda,
    const __half* __restrict__ Bh, int ldb,
    int m0, int n0) {
    uint32_t base = sb + stg * STAGE_SZ;
    #pragma unroll
    for (int p = 0; p < 4; ++p) {
        int lin = p * 256 + tid;
        int r = lin >> 3, kb = lin & 7;
        uint32_t soff = (uint32_t)(r * 128 + ((kb ^ (r & 7)) << 4));
        CP_ASYNC16(base + AH_OFF + soff, Ah + (size_t)(m0 + r) * lda + k0 + kb * 8);
        CP_ASYNC16(base + BH_OFF + soff, Bh + (size_t)(n0 + r) * ldb + k0 + kb * 8);
    }
}

__global__ __launch_bounds__(256)
void hmma_gemm(const __half* __restrict__ Ah, int lda,
               const __half* __restrict__ Bh, int ldb,
               const float* __restrict__ bias, const float* __restrict__ resid,
               float* __restrict__ Cf, __half* __restrict__ Ch,
               int ldc, int K, int gelu) {
    extern __shared__ char smem[];
    uint32_t sb = smem_u32(smem);
    int tid = threadIdx.x;
    int lane = tid & 31, wid = tid >> 5;
    int wm = wid >> 2, wn = wid & 3;
    int m0 = blockIdx.y * 128, n0 = blockIdx.x * 128;

    float acc[4][4][4];
    #pragma unroll
    for (int i = 0; i < 4; i++)
        #pragma unroll
        for (int j = 0; j < 4; j++)
            #pragma unroll
            for (int k = 0; k < 4; k++) acc[i][j][k] = 0.f;

    int a_row = (lane & 15);
    int a_kh  = (lane >> 4);
    int b_sub = (lane >> 3);
    int b_row = ((b_sub >> 1) << 3) + (lane & 7);
    int b_kh  = (b_sub & 1);

    const int nch = K >> 6;
    gemm_load_stage(sb, 0, tid, 0, Ah, lda, Bh, ldb, m0, n0);
    CP_COMMIT();
    if (nch > 1) {
        gemm_load_stage(sb, 1, tid, 64, Ah, lda, Bh, ldb, m0, n0);
        CP_COMMIT();
    }

    for (int ch = 0; ch < nch; ++ch) {
        if (ch + 2 < nch) {
            gemm_load_stage(sb, (ch + 2) % NSTAGE, tid, (ch + 2) << 6, Ah, lda, Bh, ldb, m0, n0);
            CP_COMMIT();
            CP_WAIT(2);
        } else if (ch + 1 < nch) {
            CP_WAIT(1);
        } else {
            CP_WAIT(0);
        }
        __syncthreads();

        uint32_t stg = sb + (ch % NSTAGE) * STAGE_SZ;
        #pragma unroll
        for (int ks = 0; ks < 4; ++ks) {
            uint32_t bhf[4][2];
            #pragma unroll
            for (int pair = 0; pair < 2; ++pair) {
                int row = wn * 32 + pair * 16 + b_row;
                int kb = ks * 2 + b_kh;
                uint32_t addr = stg + (uint32_t)(row * 128 + ((kb ^ (row & 7)) << 4));
                uint32_t rg[4];
                LDSM_X4(rg, addr + BH_OFF);
                bhf[pair * 2][0] = rg[0]; bhf[pair * 2][1] = rg[1];
                bhf[pair * 2 + 1][0] = rg[2]; bhf[pair * 2 + 1][1] = rg[3];
            }
            #pragma unroll
            for (int mt = 0; mt < 4; ++mt) {
                int row = wm * 64 + mt * 16 + a_row;
                int kb = ks * 2 + a_kh;
                uint32_t addr = stg + (uint32_t)(row * 128 + ((kb ^ (row & 7)) << 4));
                uint32_t ah[4];
                LDSM_X4(ah, addr + AH_OFF);
                #pragma unroll
                for (int nt = 0; nt < 4; ++nt)
                    MMA_F16(acc[mt][nt], ah, bhf[nt][0], bhf[nt][1]);
            }
        }
        __syncthreads();
    }

    int rbase = m0 + wm * 64 + (lane >> 2);
    int cbase = n0 + wn * 32 + (lane & 3) * 2;
    #pragma unroll
    for (int mt = 0; mt < 4; ++mt) {
        #pragma unroll
        for (int nt = 0; nt < 4; ++nt) {
            #pragma unroll
            for (int half = 0; half < 2; ++half) {
                int gm = rbase + mt * 16 + half * 8;
                int gn = cbase + nt * 8;
                float v0 = acc[mt][nt][half * 2 + 0];
                float v1 = acc[mt][nt][half * 2 + 1];
                if (bias) { v0 += bias[gn]; v1 += bias[gn + 1]; }
                if (gelu) {
                    v0 = 0.5f * v0 * (1.0f + erff(v0 * 0.70710678118654752f));
                    v1 = 0.5f * v1 * (1.0f + erff(v1 * 0.70710678118654752f));
                }
                size_t go = (size_t)gm * ldc + gn;
                if (resid) { v0 += resid[go]; v1 += resid[go + 1]; }
                if (Cf) {
                    *reinterpret_cast<float2*>(Cf + go) = make_float2(v0, v1);
                } else {
                    *reinterpret_cast<__half2*>(Ch + go) = __floats2half2_rn(v0, v1);
                }
            }
        }
    }
}

// ======================= attention =======================
__global__ void routing_kernel() {
    int bh = blockIdx.x;
    int i = threadIdx.x;
    __shared__ float ssk[NB][DH];
    const float* base = g_sk + (size_t)bh * NB * DH;
    for (int idx = i; idx < NB * DH; idx += NB) ssk[idx / DH][idx % DH] = base[idx];
    float sq[DH];
    const float* sqp = g_sq + ((size_t)bh * NB + i) * DH;
    #pragma unroll
    for (int e = 0; e < DH; e++) sq[e] = sqp[e];
    __syncthreads();
    const float sc = 0.17677669529663687f * (1.0f / 0.75f);
    float mx = -1e30f; int am = 0;
    for (int j = 0; j < NB; j++) {
        float d = 0.f;
        #pragma unroll
        for (int e = 0; e < DH; e++) d = fmaf(sq[e], ssk[j][e], d);
        d *= sc;
        if (d > mx) { mx = d; am = j; }
    }
    float sum = 0.f;
    for (int j = 0; j < NB; j++) {
        float d = 0.f;
        #pragma unroll
        for (int e = 0; e < DH; e++) d = fmaf(sq[e], ssk[j][e], d);
        sum += expf(d * sc - mx);
    }
    g_top[bh * NB + i] = 1.0f / sum;
    g_idx[bh * NB + i] = am;
}

// MMA flash attention: 1 block = (bucket u, head-batch bh), 4 warps x 16 q-rows.
__global__ __launch_bounds__(128)
void attn_kernel(const __half* __restrict__ qkv, __half* __restrict__ o) {
    __shared__ __half sQ[64 * 40];
    __shared__ __half sK[128 * 40];
    __shared__ __half sV[128 * 40];
    int u = blockIdx.x, bh = blockIdx.y;
    int b = bh >> 3, h = bh & 7;
    int tid = threadIdx.x, lane = tid & 31, warp = tid >> 5;
    float top = g_top[bh * NB + u];
    int ridx = g_idx[bh * NB + u];
    const __half* qg = qkv + ((size_t)(b * TT + u * BUCKET)) * QKVD + h * DH;
    const __half* kgs = qg + 256;
    const __half* kgr = qkv + ((size_t)(b * TT + ridx * BUCKET)) * QKVD + 256 + h * DH;
    uint32_t sqa = smem_u32(sQ), ska = smem_u32(sK), sva = smem_u32(sV);

    #pragma unroll
    for (int i = tid; i < 256; i += 128) {
        int r = i >> 2, cb = i & 3;
        CP_ASYNC16(sqa + r * 80 + cb * 16, qg + (size_t)r * QKVD + cb * 8);
    }
    #pragma unroll
    for (int i = tid; i < 512; i += 128) {
        int r = i >> 2, cb = i & 3;
        const __half* kr = (r < 64) ? kgr + (size_t)r * QKVD : kgs + (size_t)(r - 64) * QKVD;
        CP_ASYNC16(ska + r * 80 + cb * 16, kr + cb * 8);
        CP_ASYNC16(sva + r * 80 + cb * 16, kr + 256 + cb * 8);
    }
    CP_COMMIT(); CP_WAIT(0);
    __syncthreads();

    uint32_t qa[2][4];
    #pragma unroll
    for (int kh = 0; kh < 2; ++kh) {
        uint32_t addr = sqa + (uint32_t)((warp * 16 + (lane & 15)) * 80 + (lane >> 4) * 16 + kh * 32);
        LDSM_X4(qa[kh], addr);
    }

    float acc[16][4];
    #pragma unroll
    for (int t = 0; t < 16; t++)
        #pragma unroll
        for (int j = 0; j < 4; j++) acc[t][j] = 0.f;
    int b_sub = lane >> 3;
    int b_row = ((b_sub >> 1) << 3) + (lane & 7);
    int b_kh  = b_sub & 1;
    #pragma unroll
    for (int pair = 0; pair < 8; ++pair) {
        #pragma unroll
        for (int kh = 0; kh < 2; ++kh) {
            uint32_t addr = ska + (uint32_t)((pair * 16 + b_row) * 80 + kh * 32 + b_kh * 16);
            uint32_t rg[4];
            LDSM_X4(rg, addr);
            MMA_F16(acc[pair * 2],     qa[kh], rg[0], rg[1]);
            MMA_F16(acc[pair * 2 + 1], qa[kh], rg[2], rg[3]);
        }
    }

    const float scale = 0.17677669529663687f;
    #pragma unroll
    for (int t = 0; t < 16; t++) {
        float f = (t < 8) ? scale * top : scale;
        #pragma unroll
        for (int j = 0; j < 4; j++) acc[t][j] *= f;
    }
    float mx0 = -1e30f, mx1 = -1e30f;
    #pragma unroll
    for (int t = 0; t < 16; t++) {
        mx0 = fmaxf(mx0, fmaxf(acc[t][0], acc[t][1]));
        mx1 = fmaxf(mx1, fmaxf(acc[t][2], acc[t][3]));
    }
    #pragma unroll
    for (int off = 1; off < 4; off <<= 1) {
        mx0 = fmaxf(mx0, __shfl_xor_sync(0xffffffffu, mx0, off));
        mx1 = fmaxf(mx1, __shfl_xor_sync(0xffffffffu, mx1, off));
    }
    float s0 = 0.f, s1 = 0.f;
    #pragma unroll
    for (int t = 0; t < 16; t++) {
        acc[t][0] = __expf(acc[t][0] - mx0);
        acc[t][1] = __expf(acc[t][1] - mx0);
        acc[t][2] = __expf(acc[t][2] - mx1);
        acc[t][3] = __expf(acc[t][3] - mx1);
        s0 += acc[t][0] + acc[t][1];
        s1 += acc[t][2] + acc[t][3];
    }
    #pragma unroll
    for (int off = 1; off < 4; off <<= 1) {
        s0 += __shfl_xor_sync(0xffffffffu, s0, off);
        s1 += __shfl_xor_sync(0xffffffffu, s1, off);
    }
    float i0 = 1.0f / s0, i1 = 1.0f / s1;
    #pragma unroll
    for (int t = 0; t < 16; t++) {
        float f0 = (t < 8) ? i0 * top : i0;
        float f1 = (t < 8) ? i1 * top : i1;
        acc[t][0] *= f0; acc[t][1] *= f0;
        acc[t][2] *= f1; acc[t][3] *= f1;
    }

    float out[4][4];
    #pragma unroll
    for (int nt = 0; nt < 4; nt++)
        #pragma unroll
        for (int j = 0; j < 4; j++) out[nt][j] = 0.f;
    int v_row = (lane & 7) + ((lane >> 3) & 1) * 8;
    int v_ch  = (lane >> 4);
    #pragma unroll
    for (int s = 0; s < 8; ++s) {
        uint32_t pa[4];
        pa[0] = pack_half2(acc[2*s][0],   acc[2*s][1]);
        pa[1] = pack_half2(acc[2*s][2],   acc[2*s][3]);
        pa[2] = pack_half2(acc[2*s+1][0], acc[2*s+1][1]);
        pa[3] = pack_half2(acc[2*s+1][2], acc[2*s+1][3]);
        #pragma unroll
        for (int nh = 0; nh < 2; ++nh) {
            uint32_t addr = sva + (uint32_t)((s * 16 + v_row) * 80 + nh * 32 + v_ch * 16);
            uint32_t rg[4];
            LDSM_X4_T(rg, addr);
            MMA_F16(out[nh * 2],     pa, rg[0], rg[1]);
            MMA_F16(out[nh * 2 + 1], pa, rg[2], rg[3]);
        }
    }

    int r0 = warp * 16 + (lane >> 2);
    size_t ob = ((size_t)(b * TT + u * BUCKET + r0)) * DIMM + h * DH;
    #pragma unroll
    for (int nt = 0; nt < 4; ++nt) {
        int col = nt * 8 + (lane & 3) * 2;
        *reinterpret_cast<__half2*>(o + ob + col) = __floats2half2_rn(out[nt][0], out[nt][1]);
        *reinterpret_cast<__half2*>(o + ob + 8 * DIMM + col) = __floats2half2_rn(out[nt][2], out[nt][3]);
    }
}

// ======================= host orchestration =======================
extern "C" void kernel_launch(void* const* d_in, const int* in_sizes, int n_in,
                              void* d_out, int out_size) {
    const float* x     = (const float*)d_in[0];
    const float* pe0   = (const float*)d_in[1];
    const float* pe1   = (const float*)d_in[2];
    const float* ln1_g = (const float*)d_in[3];
    const float* ln1_b = (const float*)d_in[4];
    const float* Wq    = (const float*)d_in[5];
    const float* Wkv   = (const float*)d_in[6];
    const float* Wo    = (const float*)d_in[7];
    const float* bo    = (const float*)d_in[8];
    const float* ln2_g = (const float*)d_in[9];
    const float* ln2_b = (const float*)d_in[10];
    const float* W1    = (const float*)d_in[11];
    const float* b1    = (const float*)d_in[12];
    const float* W2    = (const float*)d_in[13];
    const float* b2    = (const float*)d_in[14];
    const float* gf    = (const float*)d_in[15];
    const float* bf    = (const float*)d_in[16];
    float* out = (float*)d_out;

    cudaFuncSetAttribute(hmma_gemm, cudaFuncAttributeMaxDynamicSharedMemorySize, GEMM_SMEM);

    float *y, *hmean;
    __half *qkv, *h, *o, *ff;
    __half *wqkv, *wo, *w1, *w2;
    cudaGetSymbolAddress((void**)&y, g_y);
    cudaGetSymbolAddress((void**)&qkv, g_qkv);
    cudaGetSymbolAddress((void**)&hmean, g_hmean);
    cudaGetSymbolAddress((void**)&h, g_h);
    cudaGetSymbolAddress((void**)&o, g_o);
    cudaGetSymbolAddress((void**)&ff, g_ff);
    cudaGetSymbolAddress((void**)&wqkv, g_wqkv);
    cudaGetSymbolAddress((void**)&wo, g_wo);
    cudaGetSymbolAddress((void**)&w1, g_w1);
    cudaGetSymbolAddress((void**)&w2, g_w2);

    dim3 tb(32, 8);
    const size_t QKV_LS = (size_t)QKVD * DIMM;
    wconv_kernel<<<dim3(DIMM / 32,   DIMM / 32, DEPTHN), tb>>>(Wq,  wqkv, DIMM, DIMM, QKV_LS);
    wconv_kernel<<<dim3(2*DIMM / 32, DIMM / 32, DEPTHN), tb>>>(Wkv, wqkv + 256 * DIMM, DIMM, 2*DIMM, QKV_LS);
    wconv_kernel<<<dim3(DIMM / 32,   DIMM / 32, DEPTHN), tb>>>(Wo,  wo, DIMM, DIMM, (size_t)DIMM * DIMM);
    wconv_kernel<<<dim3(FFD / 32,    DIMM / 32, DEPTHN), tb>>>(W1,  w1, DIMM, FFD, (size_t)DIMM * FFD);
    wconv_kernel<<<dim3(DIMM / 32,   FFD / 32,  DEPTHN), tb>>>(W2,  w2, FFD,  DIMM, (size_t)DIMM * FFD);

    dim3 tg(TT / 32, DIMM / 32, BB);
    pos_add_kernel<<<tg, tb>>>(x, pe0, pe1, y);

    for (int L = 0; L < DEPTHN; L++) {
        const float* g1 = ln1_g + (size_t)L * DIMM;
        const float* bb = ln1_b + (size_t)L * DIMM;
        const float* bo_ = bo + (size_t)L * DIMM;
        const float* bb1 = b1 + (size_t)L * FFD;
        const float* bb2 = b2 + (size_t)L * DIMM;
        size_t oqkv = (size_t)L * QKV_LS;
        size_t oo   = (size_t)L * DIMM * DIMM;
        size_t off1 = (size_t)L * DIMM * FFD;

        ln1_fused_kernel<<<NBK, 256>>>(y, h, g1, bb, hmean);
        route_gemm_kernel<<<dim3(NBK, 2), 256>>>(hmean,
            Wq + (size_t)L * DIMM * DIMM, Wkv + (size_t)L * DIMM * 2 * DIMM);
        routing_kernel<<<BHN, NB>>>();
        hmma_gemm<<<dim3(QKVD / 128, MROWS / 128), 256, GEMM_SMEM>>>(h, DIMM,
            wqkv + oqkv, DIMM, nullptr, nullptr, nullptr, qkv, QKVD, DIMM, 0);
        attn_kernel<<<dim3(NB, BHN), 128>>>(qkv, o);
        hmma_gemm<<<dim3(2, MROWS / 128), 256, GEMM_SMEM>>>(o, DIMM, wo + oo, DIMM,
            bo_, y, y, nullptr, DIMM, DIMM, 0);
        ln_h_kernel<<<MROWS / 8, 256>>>(y, h, ln2_g + (size_t)L * DIMM, ln2_b + (size_t)L * DIMM);
        hmma_gemm<<<dim3(8, MROWS / 128), 256, GEMM_SMEM>>>(h, DIMM, w1 + off1, DIMM,
            bb1, nullptr, nullptr, ff, FFD, DIMM, 1);
        hmma_gemm<<<dim3(2, MROWS / 128), 256, GEMM_SMEM>>>(ff, FFD, w2 + off1, FFD,
            bb2, y, y, nullptr, DIMM, FFD, 0);
    }

    ln_kernel<<<MROWS / 8, 256>>>(y, (float*)qkv, gf, bf);
    out_transpose_kernel<<<tg, tb>>>((float*)qkv, out);
    (void)in_sizes; (void)n_in; (void)out_size;
}